// round 7
// baseline (speedup 1.0000x reference)
#include <cuda_runtime.h>
#include <math.h>

#define NB     4
#define NQ     1024
#define DIM    256
#define NHEADS 8
#define GH     200
#define GW     200
#define NHW    (GH*GW)       // 40000
#define NROWS  (NB*NQ)       // 4096
#define NAUG   128           // 64 off | 32 attn logits | 32 pad

// Scratch (__device__ globals: allocation-free per harness rules)
__device__ float g_qoa  [NROWS * NAUG];
__device__ float g_Waug [DIM * NAUG];
__device__ float g_baug [NAUG];
__device__ float g_Wfold[512 * DIM];                     // [W_do@W_out ; W_q@W_out]
__device__ float g_bfold[DIM];
__device__ float g_gath [(size_t)NROWS * NHEADS * DIM];  // 32 MB
__device__ float g_wsum [NROWS * NHEADS];
__device__ float g_bevT [(size_t)NB * NHW * DIM];        // 164 MB
__device__ float g_samp [NROWS * DIM];

// ---------------------------------------------------------------------------
// W_aug = [ W_q@W_off | W_q@W_attn | 0 ]  (128 cols)
// ---------------------------------------------------------------------------
__global__ __launch_bounds__(256)
void prep_weights(const float* __restrict__ W_q, const float* __restrict__ W_off,
                  const float* __restrict__ W_attn, float* __restrict__ W_aug)
{
    const int id = blockIdx.x * 256 + threadIdx.x;   // 256*128
    const int k = id >> 7, n = id & 127;
    float v = 0.f;
    if (n < 64) {
        float s = 0.f;
        for (int i = 0; i < 256; i++) s = fmaf(W_q[k * 256 + i], W_off[i * 64 + n], s);
        v = s;
    } else if (n < 96) {
        const int j = n - 64;
        float s = 0.f;
        for (int i = 0; i < 256; i++) s = fmaf(W_q[k * 256 + i], W_attn[i * 32 + j], s);
        v = s;
    }
    W_aug[id] = v;
}

__global__ void prep_bias(const float* __restrict__ b_q, const float* __restrict__ b_off,
                          const float* __restrict__ b_attn,
                          const float* __restrict__ W_off, const float* __restrict__ W_attn,
                          float* __restrict__ b_aug)
{
    const int n = threadIdx.x;   // 128
    float v = 0.f;
    if (n < 64) {
        float s = b_off[n];
        for (int i = 0; i < 256; i++) s = fmaf(b_q[i], W_off[i * 64 + n], s);
        v = s;
    } else if (n < 96) {
        const int j = n - 64;
        float s = b_attn[j];
        for (int i = 0; i < 256; i++) s = fmaf(b_q[i], W_attn[i * 32 + j], s);
        v = s;
    }
    b_aug[n] = v;
}

// b_fold = (b_do + b_q) @ W_out + b_out
__global__ void prep_bfold(const float* __restrict__ b_q, const float* __restrict__ b_do,
                           const float* __restrict__ b_out, const float* __restrict__ W_out,
                           float* __restrict__ bf)
{
    const int n = threadIdx.x;   // 256
    __shared__ float bs[256];
    bs[n] = b_do[n] + b_q[n];
    __syncthreads();
    float s = b_out[n];
#pragma unroll 8
    for (int k = 0; k < 256; k++) s = fmaf(bs[k], W_out[k * 256 + n], s);
    bf[n] = s;
}

// ---------------------------------------------------------------------------
// Weight fold: Wfold[0:256]   = W_do @ W_out
//              Wfold[256:512] = W_q  @ W_out
// One block per output row; A-row in smem, W_out streamed coalesced.
// ---------------------------------------------------------------------------
__global__ __launch_bounds__(256)
void fold_kernel(const float* __restrict__ W_do, const float* __restrict__ W_q,
                 const float* __restrict__ W_out, float* __restrict__ Wfold)
{
    const int t = threadIdx.x;
    const int r = blockIdx.x & 255;
    const bool second = blockIdx.x >= 256;
    const float* Arow = (second ? W_q : W_do) + (size_t)r * 256;

    __shared__ float a[256];
    a[t] = Arow[t];
    __syncthreads();

    float s = 0.f;
#pragma unroll 8
    for (int k = 0; k < 256; k++) s = fmaf(a[k], W_out[(size_t)k * 256 + t], s);
    Wfold[(size_t)blockIdx.x * 256 + t] = s;
}

// ---------------------------------------------------------------------------
// GEMM: C[M x N] = A[M x 256] @ W[256 x N] + bias.  BM=128, BN=64, BK=16.
// ---------------------------------------------------------------------------
__global__ __launch_bounds__(256)
void gemm_v2(const float* __restrict__ A, const float* __restrict__ W,
             const float* __restrict__ bias, float* __restrict__ C, int ldc, int ldw)
{
    __shared__ float As[16][132];
    __shared__ __align__(16) float Bs[16][64];

    const int tid = threadIdx.x;
    const int tx = tid & 15, ty = tid >> 4;
    const int n0 = blockIdx.x * 64;
    const int m0 = blockIdx.y * 128;

    float acc[8][4];
#pragma unroll
    for (int i = 0; i < 8; i++)
#pragma unroll
        for (int j = 0; j < 4; j++) acc[i][j] = 0.f;

    for (int k0 = 0; k0 < 256; k0 += 16) {
        {
            const int mr = tid >> 2;
            const int kq = (tid & 3) * 4;
#pragma unroll
            for (int r = 0; r < 2; r++) {
                const int m = mr + 64 * r;
                float4 v = *(const float4*)(A + (size_t)(m0 + m) * 256 + k0 + kq);
                As[kq + 0][m] = v.x; As[kq + 1][m] = v.y;
                As[kq + 2][m] = v.z; As[kq + 3][m] = v.w;
            }
        }
        {
            const int kr = tid >> 4;
            const int nq = (tid & 15) * 4;
            *(float4*)&Bs[kr][nq] = *(const float4*)(W + (size_t)(k0 + kr) * ldw + n0 + nq);
        }
        __syncthreads();

#pragma unroll
        for (int k = 0; k < 16; k++) {
            float a[8], b[4];
#pragma unroll
            for (int i = 0; i < 4; i++) {
                a[i]     = As[k][ty * 4 + i];
                a[i + 4] = As[k][64 + ty * 4 + i];
            }
#pragma unroll
            for (int j = 0; j < 4; j++) b[j] = Bs[k][tx * 4 + j];
#pragma unroll
            for (int i = 0; i < 8; i++)
#pragma unroll
                for (int j = 0; j < 4; j++)
                    acc[i][j] = fmaf(a[i], b[j], acc[i][j]);
        }
        __syncthreads();
    }

#pragma unroll
    for (int i = 0; i < 8; i++) {
        const int m = m0 + (i < 4 ? ty * 4 + i : 64 + ty * 4 + (i - 4));
#pragma unroll
        for (int j = 0; j < 4; j++) {
            const int n = n0 + tx * 4 + j;
            C[(size_t)m * ldc + n] = acc[i][j] + bias[n];
        }
    }
}

// ---------------------------------------------------------------------------
// Dual-A GEMM (K=512): C = [A1 | A2] @ W512 + bias.  N=256, BM=64, BN=64.
// ---------------------------------------------------------------------------
__global__ __launch_bounds__(256)
void gemm_dual64(const float* __restrict__ A1, const float* __restrict__ A2,
                 const float* __restrict__ W, const float* __restrict__ bias,
                 float* __restrict__ C)
{
    __shared__ float As[16][68];
    __shared__ __align__(16) float Bs[16][64];

    const int tid = threadIdx.x;
    const int tx = tid & 15, ty = tid >> 4;
    const int n0 = blockIdx.x * 64;
    const int m0 = blockIdx.y * 64;

    float acc[4][4];
#pragma unroll
    for (int i = 0; i < 4; i++)
#pragma unroll
        for (int j = 0; j < 4; j++) acc[i][j] = 0.f;

    for (int k0 = 0; k0 < 512; k0 += 16) {
        const float* A = (k0 < 256) ? A1 : A2;
        const int kk = k0 & 255;
        {
            const int m = tid >> 2;
            const int kq = (tid & 3) * 4;
            float4 v = *(const float4*)(A + (size_t)(m0 + m) * 256 + kk + kq);
            As[kq + 0][m] = v.x; As[kq + 1][m] = v.y;
            As[kq + 2][m] = v.z; As[kq + 3][m] = v.w;
        }
        {
            const int kr = tid >> 4;
            const int nq = (tid & 15) * 4;
            *(float4*)&Bs[kr][nq] = *(const float4*)(W + (size_t)(k0 + kr) * 256 + n0 + nq);
        }
        __syncthreads();

#pragma unroll
        for (int k = 0; k < 16; k++) {
            float a[4], b[4];
#pragma unroll
            for (int i = 0; i < 4; i++) a[i] = As[k][ty * 4 + i];
#pragma unroll
            for (int j = 0; j < 4; j++) b[j] = Bs[k][tx * 4 + j];
#pragma unroll
            for (int i = 0; i < 4; i++)
#pragma unroll
                for (int j = 0; j < 4; j++)
                    acc[i][j] = fmaf(a[i], b[j], acc[i][j]);
        }
        __syncthreads();
    }

#pragma unroll
    for (int i = 0; i < 4; i++) {
        const int m = m0 + ty * 4 + i;
#pragma unroll
        for (int j = 0; j < 4; j++) {
            const int n = n0 + tx * 4 + j;
            C[(size_t)m * 256 + n] = acc[i][j] + bias[n];
        }
    }
}

// ---------------------------------------------------------------------------
// Per-batch transpose bev [C=256, HW] -> bevT [HW, C]. 32(C) x 64(HW) tiles.
// ---------------------------------------------------------------------------
__global__ __launch_bounds__(256)
void transpose_kernel(const float* __restrict__ src, float* __restrict__ dst)
{
    __shared__ float tile[32 * 65];
    const int p0 = blockIdx.x * 64;
    const int c0 = blockIdx.y * 32;
    const int tid = threadIdx.x;

#pragma unroll
    for (int l = 0; l < 2; l++) {
        const int c = l * 16 + (tid >> 4);
        const int p = (tid & 15) * 4;
        float4 v = *(const float4*)(src + (size_t)(c0 + c) * NHW + p0 + p);
        tile[c * 65 + p + 0] = v.x;
        tile[c * 65 + p + 1] = v.y;
        tile[c * 65 + p + 2] = v.z;
        tile[c * 65 + p + 3] = v.w;
    }
    __syncthreads();

#pragma unroll
    for (int l = 0; l < 2; l++) {
        const int p  = l * 32 + (tid >> 3);
        const int cq = (tid & 7) * 4;
        float4 v;
        v.x = tile[(cq + 0) * 65 + p];
        v.y = tile[(cq + 1) * 65 + p];
        v.z = tile[(cq + 2) * 65 + p];
        v.w = tile[(cq + 3) * 65 + p];
        *(float4*)(dst + (size_t)(p0 + p) * 256 + c0 + cq) = v;
    }
}

// ---------------------------------------------------------------------------
// Gather with pixel dedup (per-batch launch; row = row0 + blockIdx.x).
// ---------------------------------------------------------------------------
__global__ __launch_bounds__(256)
void gather_kernel(const float* __restrict__ ctrl, const float* __restrict__ pcr,
                   const float* __restrict__ bevT, const float* __restrict__ qoa,
                   float* __restrict__ g, float* __restrict__ wsum, int row0)
{
    const int row = row0 + blockIdx.x;
    const int b = row >> 10;
    const int t = threadIdx.x;

    __shared__ int    s_idx[128];
    __shared__ float  s_w[128];
    __shared__ float  ws[32];
    __shared__ int    hidx[256];
    __shared__ float  hw[256][8];
    __shared__ int    slots[128];
    __shared__ int    cnt;
    __shared__ float4 red4[4 * 8 * 64];   // 32KB

    hidx[t] = -1;
    {
        float* hwf = &hw[0][0];
#pragma unroll
        for (int i = 0; i < 8; i++) hwf[t + 256 * i] = 0.f;
    }
    if (t == 0) cnt = 0;

    if (t < 32) {
        const float lox = pcr[0], loy = pcr[1];
        const float spx = pcr[3] - pcr[0], spy = pcr[4] - pcr[1];
        const float* cp = ctrl + (size_t)row * 8;
        const float c0x = cp[0], c0y = cp[1], c1x = cp[2], c1y = cp[3];
        const float c2x = cp[4], c2y = cp[5], c3x = cp[6], c3y = cp[7];
        float sx = 0.f, sy = 0.f;
#pragma unroll
        for (int k = 0; k < 10; k++) {
            const float tt = (float)k / 9.0f;
            const float u = 1.0f - tt;
            const float w0 = u*u*u, w1 = 3.f*u*u*tt, w2 = 3.f*u*tt*tt, w3 = tt*tt*tt;
            const float dx = w0*c0x + w1*c1x + w2*c2x + w3*c3x;
            const float dy = w0*c0y + w1*c1y + w2*c2y + w3*c3y;
            sx += fminf(fmaxf((dx - lox) / spx, 0.01f), 0.99f);
            sy += fminf(fmaxf((dy - loy) / spy, 0.01f), 0.99f);
        }
        const float rcx = sx * 0.1f, rcy = sy * 0.1f;

        const int h = t >> 2, p = t & 3;
        const float* lg = qoa + (size_t)row * NAUG + 64 + h * 4;
        const float l0 = lg[0], l1 = lg[1], l2 = lg[2], l3 = lg[3];
        const float m = fmaxf(fmaxf(l0, l1), fmaxf(l2, l3));
        const float e0 = expf(l0 - m), e1 = expf(l1 - m), e2 = expf(l2 - m), e3 = expf(l3 - m);
        const float lp = (p == 0) ? l0 : (p == 1) ? l1 : (p == 2) ? l2 : l3;
        const float aw = expf(lp - m) / (e0 + e1 + e2 + e3);

        const float ox = qoa[(size_t)row * NAUG + h * 8 + p * 2 + 0];
        const float oy = qoa[(size_t)row * NAUG + h * 8 + p * 2 + 1];
        const float x = (rcx + ox / (float)GW) * (float)GW - 0.5f;
        const float y = (rcy + oy / (float)GH) * (float)GH - 0.5f;
        const float fx = floorf(x), fy = floorf(y);
        const int x0 = (int)fx, y0 = (int)fy;
        const int x1 = x0 + 1,  y1 = y0 + 1;
        const float wx = x - fx, wy = y - fy;
        const bool vx0 = (x0 >= 0) & (x0 < GW), vx1 = (x1 >= 0) & (x1 < GW);
        const bool vy0 = (y0 >= 0) & (y0 < GH), vy1 = (y1 >= 0) & (y1 < GH);
        const int cx0 = min(max(x0, 0), GW - 1), cx1 = min(max(x1, 0), GW - 1);
        const int cy0 = min(max(y0, 0), GH - 1), cy1 = min(max(y1, 0), GH - 1);
        const float w00 = (vy0 & vx0) ? (1.f - wx) * (1.f - wy) * aw : 0.f;
        const float w01 = (vy0 & vx1) ? wx * (1.f - wy) * aw : 0.f;
        const float w10 = (vy1 & vx0) ? (1.f - wx) * wy * aw : 0.f;
        const float w11 = (vy1 & vx1) ? wx * wy * aw : 0.f;
        s_idx[t*4+0] = cy0 * GW + cx0;  s_w[t*4+0] = w00;
        s_idx[t*4+1] = cy0 * GW + cx1;  s_w[t*4+1] = w01;
        s_idx[t*4+2] = cy1 * GW + cx0;  s_w[t*4+2] = w10;
        s_idx[t*4+3] = cy1 * GW + cx1;  s_w[t*4+3] = w11;
        ws[t] = w00 + w01 + w10 + w11;
    }
    __syncthreads();

    if (t < 128) {
        const int idx = s_idx[t];
        const float w = s_w[t];
        const int h = t >> 4;
        unsigned s = ((unsigned)idx * 2654435761u) >> 24;
        while (true) {
            int prev = atomicCAS(&hidx[s], -1, idx);
            if (prev == -1 || prev == idx) { atomicAdd(&hw[s][h], w); break; }
            s = (s + 1) & 255;
        }
    }
    __syncthreads();

    if (hidx[t] >= 0) {
        const int p = atomicAdd(&cnt, 1);
        slots[p] = t;
    }
    __syncthreads();

    const int cq = t & 63;
    const int stripe = t >> 6;
    float4 acc8[8];
#pragma unroll
    for (int h = 0; h < 8; h++) acc8[h] = make_float4(0.f, 0.f, 0.f, 0.f);

    const int n = cnt;
    const float* basep = bevT + ((size_t)b * NHW) * 256 + cq * 4;

    int i = stripe;
    for (; i + 4 < n; i += 8) {
        const int slot0 = slots[i], slot1 = slots[i + 4];
        const float4 v0 = *(const float4*)(basep + (size_t)hidx[slot0] * 256);
        const float4 v1 = *(const float4*)(basep + (size_t)hidx[slot1] * 256);
#pragma unroll
        for (int h = 0; h < 8; h++) {
            const float w0 = hw[slot0][h], w1 = hw[slot1][h];
            acc8[h].x = fmaf(w1, v1.x, fmaf(w0, v0.x, acc8[h].x));
            acc8[h].y = fmaf(w1, v1.y, fmaf(w0, v0.y, acc8[h].y));
            acc8[h].z = fmaf(w1, v1.z, fmaf(w0, v0.z, acc8[h].z));
            acc8[h].w = fmaf(w1, v1.w, fmaf(w0, v0.w, acc8[h].w));
        }
    }
    if (i < n) {
        const int slot = slots[i];
        const float4 v = *(const float4*)(basep + (size_t)hidx[slot] * 256);
#pragma unroll
        for (int h = 0; h < 8; h++) {
            const float w = hw[slot][h];
            acc8[h].x = fmaf(w, v.x, acc8[h].x);
            acc8[h].y = fmaf(w, v.y, acc8[h].y);
            acc8[h].z = fmaf(w, v.z, acc8[h].z);
            acc8[h].w = fmaf(w, v.w, acc8[h].w);
        }
    }
#pragma unroll
    for (int h = 0; h < 8; h++)
        red4[(stripe * 8 + h) * 64 + cq] = acc8[h];
    __syncthreads();

#pragma unroll
    for (int j = 0; j < 2; j++) {
        const int pos = t + j * 256;
        const int h = pos >> 6, q = pos & 63;
        float4 a = red4[(0 * 8 + h) * 64 + q];
        const float4 b1 = red4[(1 * 8 + h) * 64 + q];
        const float4 b2 = red4[(2 * 8 + h) * 64 + q];
        const float4 b3 = red4[(3 * 8 + h) * 64 + q];
        a.x += b1.x + b2.x + b3.x;
        a.y += b1.y + b2.y + b3.y;
        a.z += b1.z + b2.z + b3.z;
        a.w += b1.w + b2.w + b3.w;
        *(float4*)(g + ((size_t)row * 8 + h) * 256 + q * 4) = a;
    }

    if (t < 8)
        wsum[(size_t)row * 8 + t] = ws[t*4] + ws[t*4+1] + ws[t*4+2] + ws[t*4+3];
}

// ---------------------------------------------------------------------------
// Block-diagonal projection.
// ---------------------------------------------------------------------------
__global__ __launch_bounds__(256)
void proj_kernel(const float* __restrict__ g, const float* __restrict__ wsum,
                 const float* __restrict__ W_val, const float* __restrict__ b_val,
                 float* __restrict__ samp)
{
    const int h  = blockIdx.y;
    const int r0 = blockIdx.x * 128;
    const int t  = threadIdx.x;
    const int d = t & 31, rg = t >> 5;

    __shared__ float Ws[256 * 32];
    __shared__ float As[128 * 36];

#pragma unroll
    for (int i = 0; i < 32; i++) {
        const int k = i * 8 + (t >> 5);
        Ws[k * 32 + d] = W_val[(size_t)k * 256 + h * 32 + d];
    }
    const float bv = b_val[h * 32 + d];

    float acc[16];
#pragma unroll
    for (int r = 0; r < 16; r++) acc[r] = 0.f;

    for (int kt = 0; kt < 8; kt++) {
        __syncthreads();
        {
            const int i = t >> 1, half = t & 1;
            const float* src = g + ((size_t)(r0 + i) * 8 + h) * 256 + kt * 32 + half * 16;
            float* dst = &As[i * 36 + half * 16];
#pragma unroll
            for (int q = 0; q < 4; q++)
                *(float4*)(dst + q * 4) = *(const float4*)(src + q * 4);
        }
        __syncthreads();

#pragma unroll
        for (int k = 0; k < 32; k++) {
            const float wv = Ws[(kt * 32 + k) * 32 + d];
#pragma unroll
            for (int r = 0; r < 16; r++)
                acc[r] = fmaf(As[(rg * 16 + r) * 36 + k], wv, acc[r]);
        }
    }

#pragma unroll
    for (int r = 0; r < 16; r++) {
        const int row = r0 + rg * 16 + r;
        samp[(size_t)row * 256 + h * 32 + d] = acc[r] + wsum[(size_t)row * 8 + h] * bv;
    }
}

// ---------------------------------------------------------------------------
extern "C" void kernel_launch(void* const* d_in, const int* in_sizes, int n_in,
                              void* d_out, int out_size)
{
    const float* query_embed = (const float*)d_in[0];
    const float* ctrl        = (const float*)d_in[1];
    const float* bev         = (const float*)d_in[2];
    /* d_in[3] spatial_shapes unused */
    const float* pc_range    = (const float*)d_in[4];
    const float* W_q   = (const float*)d_in[5];
    const float* b_q   = (const float*)d_in[6];
    const float* W_val = (const float*)d_in[7];
    const float* b_val = (const float*)d_in[8];
    const float* W_off = (const float*)d_in[9];
    const float* b_off = (const float*)d_in[10];
    const float* W_attn = (const float*)d_in[11];
    const float* b_attn = (const float*)d_in[12];
    const float* W_do  = (const float*)d_in[13];
    const float* b_do  = (const float*)d_in[14];
    const float* W_out = (const float*)d_in[15];
    const float* b_out = (const float*)d_in[16];
    float* out = (float*)d_out;

    float *pqoa, *pWaug, *pbaug, *pWfold, *pbfold, *pg, *pws, *pbT, *ps;
    cudaGetSymbolAddress((void**)&pqoa,  g_qoa);
    cudaGetSymbolAddress((void**)&pWaug, g_Waug);
    cudaGetSymbolAddress((void**)&pbaug, g_baug);
    cudaGetSymbolAddress((void**)&pWfold, g_Wfold);
    cudaGetSymbolAddress((void**)&pbfold, g_bfold);
    cudaGetSymbolAddress((void**)&pg,    g_gath);
    cudaGetSymbolAddress((void**)&pws,   g_wsum);
    cudaGetSymbolAddress((void**)&pbT,   g_bevT);
    cudaGetSymbolAddress((void**)&ps,    g_samp);

    static cudaStream_t s1 = nullptr, s2 = nullptr;
    static cudaEvent_t evFork = nullptr, evS2 = nullptr;
    static cudaEvent_t evT[NB] = {nullptr, nullptr, nullptr, nullptr};
    if (s1 == nullptr) {
        cudaStreamCreateWithFlags(&s1, cudaStreamNonBlocking);
        cudaStreamCreateWithFlags(&s2, cudaStreamNonBlocking);
        cudaEventCreateWithFlags(&evFork, cudaEventDisableTiming);
        cudaEventCreateWithFlags(&evS2,   cudaEventDisableTiming);
        for (int b = 0; b < NB; b++)
            cudaEventCreateWithFlags(&evT[b], cudaEventDisableTiming);
    }

    cudaEventRecord(evFork, 0);
    cudaStreamWaitEvent(s1, evFork, 0);
    cudaStreamWaitEvent(s2, evFork, 0);

    // s1: per-batch transposes (DRAM-bound), event per batch
    for (int b = 0; b < NB; b++) {
        transpose_kernel<<<dim3(NHW / 64, DIM / 32), 256, 0, s1>>>(
            bev + (size_t)b * DIM * NHW, pbT + (size_t)b * NHW * DIM);
        cudaEventRecord(evT[b], s1);
    }

    // s2: weight folds (fast dedicated kernel) + bias fold
    prep_bfold<<<1, 256, 0, s2>>>(b_q, b_do, b_out, W_out, pbfold);
    fold_kernel<<<512, 256, 0, s2>>>(W_do, W_q, W_out, pWfold);
    cudaEventRecord(evS2, s2);

    // main: offsets/logits path
    prep_weights<<<(DIM * NAUG) / 256, 256>>>(W_q, W_off, W_attn, pWaug);
    prep_bias<<<1, NAUG>>>(b_q, b_off, b_attn, W_off, W_attn, pbaug);
    gemm_v2<<<dim3(NAUG / 64, NROWS / 128), 256>>>(
        query_embed, pWaug, pbaug, pqoa, NAUG, NAUG);

    // per-batch gathers, each gated only on its transpose
    for (int b = 0; b < NB; b++) {
        cudaStreamWaitEvent(0, evT[b], 0);
        gather_kernel<<<NQ, 256>>>(ctrl, pc_range, pbT, pqoa, pg, pws, b * NQ);
    }

    // per-head projection
    proj_kernel<<<dim3(NROWS / 128, NHEADS), 256>>>(pg, pws, W_val, b_val, ps);

    cudaStreamWaitEvent(0, evS2, 0);

    // out = samp@(W_do W_out) + qe@(W_q W_out) + b_fold
    gemm_dual64<<<dim3(DIM / 64, NROWS / 64), 256>>>(
        ps, query_embed, pWfold, pbfold, out);
}

// round 8
// speedup vs baseline: 1.0620x; 1.0620x over previous
#include <cuda_runtime.h>
#include <math.h>

#define NB     4
#define NQ     1024
#define DIM    256
#define NHEADS 8
#define GH     200
#define GW     200
#define NHW    (GH*GW)       // 40000
#define NROWS  (NB*NQ)       // 4096
#define NAUG   128           // 64 off | 32 attn logits | 32 pad

// Scratch (__device__ globals: allocation-free per harness rules)
__device__ float g_qoa  [NROWS * NAUG];
__device__ float g_Waug [DIM * NAUG];
__device__ float g_baug [NAUG];
__device__ float g_Wfold[512 * DIM];                     // [W_do@W_out ; W_q@W_out]
__device__ float g_bfold[DIM];
__device__ float g_gath [(size_t)NROWS * NHEADS * DIM];  // 32 MB
__device__ float g_wsum [NROWS * NHEADS];
__device__ float g_bevT [(size_t)NB * NHW * DIM];        // 164 MB
__device__ float g_samp [NROWS * DIM];

// ---------------------------------------------------------------------------
// W_aug = [ W_q@W_off | W_q@W_attn | 0 ]  (128 cols)
// ---------------------------------------------------------------------------
__global__ __launch_bounds__(256)
void prep_weights(const float* __restrict__ W_q, const float* __restrict__ W_off,
                  const float* __restrict__ W_attn, float* __restrict__ W_aug)
{
    const int id = blockIdx.x * 256 + threadIdx.x;   // 256*128
    const int k = id >> 7, n = id & 127;
    float v = 0.f;
    if (n < 64) {
        float s = 0.f;
        for (int i = 0; i < 256; i++) s = fmaf(W_q[k * 256 + i], W_off[i * 64 + n], s);
        v = s;
    } else if (n < 96) {
        const int j = n - 64;
        float s = 0.f;
        for (int i = 0; i < 256; i++) s = fmaf(W_q[k * 256 + i], W_attn[i * 32 + j], s);
        v = s;
    }
    W_aug[id] = v;
}

__global__ void prep_bias(const float* __restrict__ b_q, const float* __restrict__ b_off,
                          const float* __restrict__ b_attn,
                          const float* __restrict__ W_off, const float* __restrict__ W_attn,
                          float* __restrict__ b_aug)
{
    const int n = threadIdx.x;   // 128
    float v = 0.f;
    if (n < 64) {
        float s = b_off[n];
        for (int i = 0; i < 256; i++) s = fmaf(b_q[i], W_off[i * 64 + n], s);
        v = s;
    } else if (n < 96) {
        const int j = n - 64;
        float s = b_attn[j];
        for (int i = 0; i < 256; i++) s = fmaf(b_q[i], W_attn[i * 32 + j], s);
        v = s;
    }
    b_aug[n] = v;
}

// b_fold = (b_do + b_q) @ W_out + b_out
__global__ void prep_bfold(const float* __restrict__ b_q, const float* __restrict__ b_do,
                           const float* __restrict__ b_out, const float* __restrict__ W_out,
                           float* __restrict__ bf)
{
    const int n = threadIdx.x;   // 256
    __shared__ float bs[256];
    bs[n] = b_do[n] + b_q[n];
    __syncthreads();
    float s = b_out[n];
#pragma unroll 8
    for (int k = 0; k < 256; k++) s = fmaf(bs[k], W_out[k * 256 + n], s);
    bf[n] = s;
}

// ---------------------------------------------------------------------------
// Weight fold: Wfold[0:256] = W_do @ W_out ; Wfold[256:512] = W_q @ W_out
// One block per output row; A-row in smem, W_out streamed coalesced.
// ---------------------------------------------------------------------------
__global__ __launch_bounds__(256)
void fold_kernel(const float* __restrict__ W_do, const float* __restrict__ W_q,
                 const float* __restrict__ W_out, float* __restrict__ Wfold)
{
    const int t = threadIdx.x;
    const int r = blockIdx.x & 255;
    const bool second = blockIdx.x >= 256;
    const float* Arow = (second ? W_q : W_do) + (size_t)r * 256;

    __shared__ float a[256];
    a[t] = Arow[t];
    __syncthreads();

    float s = 0.f;
#pragma unroll 8
    for (int k = 0; k < 256; k++) s = fmaf(a[k], W_out[(size_t)k * 256 + t], s);
    Wfold[(size_t)blockIdx.x * 256 + t] = s;
}

// ---------------------------------------------------------------------------
// GEMM: C[M x N] = A[M x 256] @ W[256 x N] + bias.  BM=128, BN=64, BK=16.
// ---------------------------------------------------------------------------
__global__ __launch_bounds__(256)
void gemm_v2(const float* __restrict__ A, const float* __restrict__ W,
             const float* __restrict__ bias, float* __restrict__ C, int ldc, int ldw)
{
    __shared__ float As[16][132];
    __shared__ __align__(16) float Bs[16][64];

    const int tid = threadIdx.x;
    const int tx = tid & 15, ty = tid >> 4;
    const int n0 = blockIdx.x * 64;
    const int m0 = blockIdx.y * 128;

    float acc[8][4];
#pragma unroll
    for (int i = 0; i < 8; i++)
#pragma unroll
        for (int j = 0; j < 4; j++) acc[i][j] = 0.f;

    for (int k0 = 0; k0 < 256; k0 += 16) {
        {
            const int mr = tid >> 2;
            const int kq = (tid & 3) * 4;
#pragma unroll
            for (int r = 0; r < 2; r++) {
                const int m = mr + 64 * r;
                float4 v = *(const float4*)(A + (size_t)(m0 + m) * 256 + k0 + kq);
                As[kq + 0][m] = v.x; As[kq + 1][m] = v.y;
                As[kq + 2][m] = v.z; As[kq + 3][m] = v.w;
            }
        }
        {
            const int kr = tid >> 4;
            const int nq = (tid & 15) * 4;
            *(float4*)&Bs[kr][nq] = *(const float4*)(W + (size_t)(k0 + kr) * ldw + n0 + nq);
        }
        __syncthreads();

#pragma unroll
        for (int k = 0; k < 16; k++) {
            float a[8], b[4];
#pragma unroll
            for (int i = 0; i < 4; i++) {
                a[i]     = As[k][ty * 4 + i];
                a[i + 4] = As[k][64 + ty * 4 + i];
            }
#pragma unroll
            for (int j = 0; j < 4; j++) b[j] = Bs[k][tx * 4 + j];
#pragma unroll
            for (int i = 0; i < 8; i++)
#pragma unroll
                for (int j = 0; j < 4; j++)
                    acc[i][j] = fmaf(a[i], b[j], acc[i][j]);
        }
        __syncthreads();
    }

#pragma unroll
    for (int i = 0; i < 8; i++) {
        const int m = m0 + (i < 4 ? ty * 4 + i : 64 + ty * 4 + (i - 4));
#pragma unroll
        for (int j = 0; j < 4; j++) {
            const int n = n0 + tx * 4 + j;
            C[(size_t)m * ldc + n] = acc[i][j] + bias[n];
        }
    }
}

// ---------------------------------------------------------------------------
// Dual-A GEMM (K=512): C = [A1 | A2] @ W512 + bias.  N=256, BM=64, BN=64.
// ---------------------------------------------------------------------------
__global__ __launch_bounds__(256)
void gemm_dual64(const float* __restrict__ A1, const float* __restrict__ A2,
                 const float* __restrict__ W, const float* __restrict__ bias,
                 float* __restrict__ C)
{
    __shared__ float As[16][68];
    __shared__ __align__(16) float Bs[16][64];

    const int tid = threadIdx.x;
    const int tx = tid & 15, ty = tid >> 4;
    const int n0 = blockIdx.x * 64;
    const int m0 = blockIdx.y * 64;

    float acc[4][4];
#pragma unroll
    for (int i = 0; i < 4; i++)
#pragma unroll
        for (int j = 0; j < 4; j++) acc[i][j] = 0.f;

    for (int k0 = 0; k0 < 512; k0 += 16) {
        const float* A = (k0 < 256) ? A1 : A2;
        const int kk = k0 & 255;
        {
            const int m = tid >> 2;
            const int kq = (tid & 3) * 4;
            float4 v = *(const float4*)(A + (size_t)(m0 + m) * 256 + kk + kq);
            As[kq + 0][m] = v.x; As[kq + 1][m] = v.y;
            As[kq + 2][m] = v.z; As[kq + 3][m] = v.w;
        }
        {
            const int kr = tid >> 4;
            const int nq = (tid & 15) * 4;
            *(float4*)&Bs[kr][nq] = *(const float4*)(W + (size_t)(k0 + kr) * 256 + n0 + nq);
        }
        __syncthreads();

#pragma unroll
        for (int k = 0; k < 16; k++) {
            float a[4], b[4];
#pragma unroll
            for (int i = 0; i < 4; i++) a[i] = As[k][ty * 4 + i];
#pragma unroll
            for (int j = 0; j < 4; j++) b[j] = Bs[k][tx * 4 + j];
#pragma unroll
            for (int i = 0; i < 4; i++)
#pragma unroll
                for (int j = 0; j < 4; j++)
                    acc[i][j] = fmaf(a[i], b[j], acc[i][j]);
        }
        __syncthreads();
    }

#pragma unroll
    for (int i = 0; i < 4; i++) {
        const int m = m0 + ty * 4 + i;
#pragma unroll
        for (int j = 0; j < 4; j++) {
            const int n = n0 + tx * 4 + j;
            C[(size_t)m * 256 + n] = acc[i][j] + bias[n];
        }
    }
}

// ---------------------------------------------------------------------------
// Monolithic transpose bev [B, C=256, HW] -> bevT [B, HW, C] (round-6 version).
// ---------------------------------------------------------------------------
__global__ __launch_bounds__(256)
void transpose_kernel(const float* __restrict__ src, float* __restrict__ dst)
{
    __shared__ float tile[32 * 65];
    const int b  = blockIdx.z;
    const int p0 = blockIdx.x * 64;
    const int c0 = blockIdx.y * 32;
    const int tid = threadIdx.x;

#pragma unroll
    for (int l = 0; l < 2; l++) {
        const int c = l * 16 + (tid >> 4);
        const int p = (tid & 15) * 4;
        float4 v = *(const float4*)(src + ((size_t)(b * 256 + c0 + c)) * NHW + p0 + p);
        tile[c * 65 + p + 0] = v.x;
        tile[c * 65 + p + 1] = v.y;
        tile[c * 65 + p + 2] = v.z;
        tile[c * 65 + p + 3] = v.w;
    }
    __syncthreads();

#pragma unroll
    for (int l = 0; l < 2; l++) {
        const int p  = l * 32 + (tid >> 3);
        const int cq = (tid & 7) * 4;
        float4 v;
        v.x = tile[(cq + 0) * 65 + p];
        v.y = tile[(cq + 1) * 65 + p];
        v.z = tile[(cq + 2) * 65 + p];
        v.w = tile[(cq + 3) * 65 + p];
        *(float4*)(dst + ((size_t)b * NHW + p0 + p) * 256 + c0 + cq) = v;
    }
}

// ---------------------------------------------------------------------------
// Gather with pixel dedup. Single launch, block per row.
// ---------------------------------------------------------------------------
__global__ __launch_bounds__(256)
void gather_kernel(const float* __restrict__ ctrl, const float* __restrict__ pcr,
                   const float* __restrict__ bevT, const float* __restrict__ qoa,
                   float* __restrict__ g, float* __restrict__ wsum)
{
    const int row = blockIdx.x;
    const int b = row >> 10;
    const int t = threadIdx.x;

    __shared__ int    s_idx[128];
    __shared__ float  s_w[128];
    __shared__ float  ws[32];
    __shared__ int    hidx[256];
    __shared__ float  hw[256][8];
    __shared__ int    slots[128];
    __shared__ int    cnt;
    __shared__ float4 red4[4 * 8 * 64];   // 32KB

    hidx[t] = -1;
    {
        float* hwf = &hw[0][0];
#pragma unroll
        for (int i = 0; i < 8; i++) hwf[t + 256 * i] = 0.f;
    }
    if (t == 0) cnt = 0;

    if (t < 32) {
        const float lox = pcr[0], loy = pcr[1];
        const float spx = pcr[3] - pcr[0], spy = pcr[4] - pcr[1];
        const float* cp = ctrl + (size_t)row * 8;
        const float c0x = cp[0], c0y = cp[1], c1x = cp[2], c1y = cp[3];
        const float c2x = cp[4], c2y = cp[5], c3x = cp[6], c3y = cp[7];
        float sx = 0.f, sy = 0.f;
#pragma unroll
        for (int k = 0; k < 10; k++) {
            const float tt = (float)k / 9.0f;
            const float u = 1.0f - tt;
            const float w0 = u*u*u, w1 = 3.f*u*u*tt, w2 = 3.f*u*tt*tt, w3 = tt*tt*tt;
            const float dx = w0*c0x + w1*c1x + w2*c2x + w3*c3x;
            const float dy = w0*c0y + w1*c1y + w2*c2y + w3*c3y;
            sx += fminf(fmaxf((dx - lox) / spx, 0.01f), 0.99f);
            sy += fminf(fmaxf((dy - loy) / spy, 0.01f), 0.99f);
        }
        const float rcx = sx * 0.1f, rcy = sy * 0.1f;

        const int h = t >> 2, p = t & 3;
        const float* lg = qoa + (size_t)row * NAUG + 64 + h * 4;
        const float l0 = lg[0], l1 = lg[1], l2 = lg[2], l3 = lg[3];
        const float m = fmaxf(fmaxf(l0, l1), fmaxf(l2, l3));
        const float e0 = expf(l0 - m), e1 = expf(l1 - m), e2 = expf(l2 - m), e3 = expf(l3 - m);
        const float lp = (p == 0) ? l0 : (p == 1) ? l1 : (p == 2) ? l2 : l3;
        const float aw = expf(lp - m) / (e0 + e1 + e2 + e3);

        const float ox = qoa[(size_t)row * NAUG + h * 8 + p * 2 + 0];
        const float oy = qoa[(size_t)row * NAUG + h * 8 + p * 2 + 1];
        const float x = (rcx + ox / (float)GW) * (float)GW - 0.5f;
        const float y = (rcy + oy / (float)GH) * (float)GH - 0.5f;
        const float fx = floorf(x), fy = floorf(y);
        const int x0 = (int)fx, y0 = (int)fy;
        const int x1 = x0 + 1,  y1 = y0 + 1;
        const float wx = x - fx, wy = y - fy;
        const bool vx0 = (x0 >= 0) & (x0 < GW), vx1 = (x1 >= 0) & (x1 < GW);
        const bool vy0 = (y0 >= 0) & (y0 < GH), vy1 = (y1 >= 0) & (y1 < GH);
        const int cx0 = min(max(x0, 0), GW - 1), cx1 = min(max(x1, 0), GW - 1);
        const int cy0 = min(max(y0, 0), GH - 1), cy1 = min(max(y1, 0), GH - 1);
        const float w00 = (vy0 & vx0) ? (1.f - wx) * (1.f - wy) * aw : 0.f;
        const float w01 = (vy0 & vx1) ? wx * (1.f - wy) * aw : 0.f;
        const float w10 = (vy1 & vx0) ? (1.f - wx) * wy * aw : 0.f;
        const float w11 = (vy1 & vx1) ? wx * wy * aw : 0.f;
        s_idx[t*4+0] = cy0 * GW + cx0;  s_w[t*4+0] = w00;
        s_idx[t*4+1] = cy0 * GW + cx1;  s_w[t*4+1] = w01;
        s_idx[t*4+2] = cy1 * GW + cx0;  s_w[t*4+2] = w10;
        s_idx[t*4+3] = cy1 * GW + cx1;  s_w[t*4+3] = w11;
        ws[t] = w00 + w01 + w10 + w11;
    }
    __syncthreads();

    if (t < 128) {
        const int idx = s_idx[t];
        const float w = s_w[t];
        const int h = t >> 4;
        unsigned s = ((unsigned)idx * 2654435761u) >> 24;
        while (true) {
            int prev = atomicCAS(&hidx[s], -1, idx);
            if (prev == -1 || prev == idx) { atomicAdd(&hw[s][h], w); break; }
            s = (s + 1) & 255;
        }
    }
    __syncthreads();

    if (hidx[t] >= 0) {
        const int p = atomicAdd(&cnt, 1);
        slots[p] = t;
    }
    __syncthreads();

    const int cq = t & 63;
    const int stripe = t >> 6;
    float4 acc8[8];
#pragma unroll
    for (int h = 0; h < 8; h++) acc8[h] = make_float4(0.f, 0.f, 0.f, 0.f);

    const int n = cnt;
    const float* basep = bevT + ((size_t)b * NHW) * 256 + cq * 4;

    int i = stripe;
    // 4-deep MLP: fetch 4 pixels, then FMA
    for (; i + 12 < n; i += 16) {
        const int sl0 = slots[i], sl1 = slots[i + 4], sl2 = slots[i + 8], sl3 = slots[i + 12];
        const float4 v0 = *(const float4*)(basep + (size_t)hidx[sl0] * 256);
        const float4 v1 = *(const float4*)(basep + (size_t)hidx[sl1] * 256);
        const float4 v2 = *(const float4*)(basep + (size_t)hidx[sl2] * 256);
        const float4 v3 = *(const float4*)(basep + (size_t)hidx[sl3] * 256);
#pragma unroll
        for (int h = 0; h < 8; h++) {
            const float w0 = hw[sl0][h], w1 = hw[sl1][h], w2 = hw[sl2][h], w3 = hw[sl3][h];
            acc8[h].x = fmaf(w3, v3.x, fmaf(w2, v2.x, fmaf(w1, v1.x, fmaf(w0, v0.x, acc8[h].x))));
            acc8[h].y = fmaf(w3, v3.y, fmaf(w2, v2.y, fmaf(w1, v1.y, fmaf(w0, v0.y, acc8[h].y))));
            acc8[h].z = fmaf(w3, v3.z, fmaf(w2, v2.z, fmaf(w1, v1.z, fmaf(w0, v0.z, acc8[h].z))));
            acc8[h].w = fmaf(w3, v3.w, fmaf(w2, v2.w, fmaf(w1, v1.w, fmaf(w0, v0.w, acc8[h].w))));
        }
    }
    for (; i < n; i += 4) {
        const int slot = slots[i];
        const float4 v = *(const float4*)(basep + (size_t)hidx[slot] * 256);
#pragma unroll
        for (int h = 0; h < 8; h++) {
            const float w = hw[slot][h];
            acc8[h].x = fmaf(w, v.x, acc8[h].x);
            acc8[h].y = fmaf(w, v.y, acc8[h].y);
            acc8[h].z = fmaf(w, v.z, acc8[h].z);
            acc8[h].w = fmaf(w, v.w, acc8[h].w);
        }
    }
#pragma unroll
    for (int h = 0; h < 8; h++)
        red4[(stripe * 8 + h) * 64 + cq] = acc8[h];
    __syncthreads();

#pragma unroll
    for (int j = 0; j < 2; j++) {
        const int pos = t + j * 256;
        const int h = pos >> 6, q = pos & 63;
        float4 a = red4[(0 * 8 + h) * 64 + q];
        const float4 b1 = red4[(1 * 8 + h) * 64 + q];
        const float4 b2 = red4[(2 * 8 + h) * 64 + q];
        const float4 b3 = red4[(3 * 8 + h) * 64 + q];
        a.x += b1.x + b2.x + b3.x;
        a.y += b1.y + b2.y + b3.y;
        a.z += b1.z + b2.z + b3.z;
        a.w += b1.w + b2.w + b3.w;
        *(float4*)(g + ((size_t)row * 8 + h) * 256 + q * 4) = a;
    }

    if (t < 8)
        wsum[(size_t)row * 8 + t] = ws[t*4] + ws[t*4+1] + ws[t*4+2] + ws[t*4+3];
}

// ---------------------------------------------------------------------------
// Block-diagonal projection.
// ---------------------------------------------------------------------------
__global__ __launch_bounds__(256)
void proj_kernel(const float* __restrict__ g, const float* __restrict__ wsum,
                 const float* __restrict__ W_val, const float* __restrict__ b_val,
                 float* __restrict__ samp)
{
    const int h  = blockIdx.y;
    const int r0 = blockIdx.x * 128;
    const int t  = threadIdx.x;
    const int d = t & 31, rg = t >> 5;

    __shared__ float Ws[256 * 32];
    __shared__ float As[128 * 36];

#pragma unroll
    for (int i = 0; i < 32; i++) {
        const int k = i * 8 + (t >> 5);
        Ws[k * 32 + d] = W_val[(size_t)k * 256 + h * 32 + d];
    }
    const float bv = b_val[h * 32 + d];

    float acc[16];
#pragma unroll
    for (int r = 0; r < 16; r++) acc[r] = 0.f;

    for (int kt = 0; kt < 8; kt++) {
        __syncthreads();
        {
            const int i = t >> 1, half = t & 1;
            const float* src = g + ((size_t)(r0 + i) * 8 + h) * 256 + kt * 32 + half * 16;
            float* dst = &As[i * 36 + half * 16];
#pragma unroll
            for (int q = 0; q < 4; q++)
                *(float4*)(dst + q * 4) = *(const float4*)(src + q * 4);
        }
        __syncthreads();

#pragma unroll
        for (int k = 0; k < 32; k++) {
            const float wv = Ws[(kt * 32 + k) * 32 + d];
#pragma unroll
            for (int r = 0; r < 16; r++)
                acc[r] = fmaf(As[(rg * 16 + r) * 36 + k], wv, acc[r]);
        }
    }

#pragma unroll
    for (int r = 0; r < 16; r++) {
        const int row = r0 + rg * 16 + r;
        samp[(size_t)row * 256 + h * 32 + d] = acc[r] + wsum[(size_t)row * 8 + h] * bv;
    }
}

// ---------------------------------------------------------------------------
extern "C" void kernel_launch(void* const* d_in, const int* in_sizes, int n_in,
                              void* d_out, int out_size)
{
    const float* query_embed = (const float*)d_in[0];
    const float* ctrl        = (const float*)d_in[1];
    const float* bev         = (const float*)d_in[2];
    /* d_in[3] spatial_shapes unused */
    const float* pc_range    = (const float*)d_in[4];
    const float* W_q   = (const float*)d_in[5];
    const float* b_q   = (const float*)d_in[6];
    const float* W_val = (const float*)d_in[7];
    const float* b_val = (const float*)d_in[8];
    const float* W_off = (const float*)d_in[9];
    const float* b_off = (const float*)d_in[10];
    const float* W_attn = (const float*)d_in[11];
    const float* b_attn = (const float*)d_in[12];
    const float* W_do  = (const float*)d_in[13];
    const float* b_do  = (const float*)d_in[14];
    const float* W_out = (const float*)d_in[15];
    const float* b_out = (const float*)d_in[16];
    float* out = (float*)d_out;

    float *pqoa, *pWaug, *pbaug, *pWfold, *pbfold, *pg, *pws, *pbT, *ps;
    cudaGetSymbolAddress((void**)&pqoa,  g_qoa);
    cudaGetSymbolAddress((void**)&pWaug, g_Waug);
    cudaGetSymbolAddress((void**)&pbaug, g_baug);
    cudaGetSymbolAddress((void**)&pWfold, g_Wfold);
    cudaGetSymbolAddress((void**)&pbfold, g_bfold);
    cudaGetSymbolAddress((void**)&pg,    g_gath);
    cudaGetSymbolAddress((void**)&pws,   g_wsum);
    cudaGetSymbolAddress((void**)&pbT,   g_bevT);
    cudaGetSymbolAddress((void**)&ps,    g_samp);

    static cudaStream_t s1 = nullptr, s2 = nullptr;
    static cudaEvent_t evFork = nullptr, evT = nullptr, evS2 = nullptr;
    if (s1 == nullptr) {
        cudaStreamCreateWithFlags(&s1, cudaStreamNonBlocking);
        cudaStreamCreateWithFlags(&s2, cudaStreamNonBlocking);
        cudaEventCreateWithFlags(&evFork, cudaEventDisableTiming);
        cudaEventCreateWithFlags(&evT,    cudaEventDisableTiming);
        cudaEventCreateWithFlags(&evS2,   cudaEventDisableTiming);
    }

    cudaEventRecord(evFork, 0);
    cudaStreamWaitEvent(s1, evFork, 0);
    cudaStreamWaitEvent(s2, evFork, 0);

    // s1: monolithic DRAM-bound transpose (74% of HBM peak as one launch)
    transpose_kernel<<<dim3(NHW / 64, DIM / 32, NB), 256, 0, s1>>>(bev, pbT);
    cudaEventRecord(evT, s1);

    // s2: fast weight/bias folds
    prep_bfold<<<1, 256, 0, s2>>>(b_q, b_do, b_out, W_out, pbfold);
    fold_kernel<<<512, 256, 0, s2>>>(W_do, W_q, W_out, pWfold);
    cudaEventRecord(evS2, s2);

    // main: offsets/logits path
    prep_weights<<<(DIM * NAUG) / 256, 256>>>(W_q, W_off, W_attn, pWaug);
    prep_bias<<<1, NAUG>>>(b_q, b_off, b_attn, W_off, W_attn, pbaug);
    gemm_v2<<<dim3(NAUG / 64, NROWS / 128), 256>>>(
        query_embed, pWaug, pbaug, pqoa, NAUG, NAUG);

    cudaStreamWaitEvent(0, evT, 0);

    // gather (dedup, MLP-4) + per-head projection
    gather_kernel<<<NROWS, 256>>>(ctrl, pc_range, pbT, pqoa, pg, pws);
    proj_kernel<<<dim3(NROWS / 128, NHEADS), 256>>>(pg, pws, W_val, b_val, ps);

    cudaStreamWaitEvent(0, evS2, 0);

    // out = samp@(W_do W_out) + qe@(W_q W_out) + b_fold
    gemm_dual64<<<dim3(DIM / 64, NROWS / 64), 256>>>(
        ps, query_embed, pWfold, pbfold, out);
}

// round 9
// speedup vs baseline: 1.1983x; 1.1283x over previous
#include <cuda_runtime.h>
#include <cuda_fp16.h>
#include <math.h>

#define NB     4
#define NQ     1024
#define DIM    256
#define NHEADS 8
#define GH     200
#define GW     200
#define NHW    (GH*GW)       // 40000
#define NROWS  (NB*NQ)       // 4096
#define NAUG   128           // 64 off | 32 attn logits | 32 pad

// Scratch (__device__ globals: allocation-free per harness rules)
__device__ float  g_qoa  [NROWS * NAUG];
__device__ float  g_Waug [DIM * NAUG];
__device__ float  g_baug [NAUG];
__device__ float  g_Wfold[512 * DIM];                     // [W_do@W_out ; W_q@W_out]
__device__ float  g_bfold[DIM];
__device__ float  g_gath [(size_t)NROWS * NHEADS * DIM];  // 32 MB
__device__ float  g_wsum [NROWS * NHEADS];
__device__ __half g_bevTh[(size_t)NB * NHW * DIM];        // 82 MB, fp16 [B, HW, C]
__device__ float  g_samp [NROWS * DIM];

// ---------------------------------------------------------------------------
// W_aug = [ W_q@W_off | W_q@W_attn | 0 ] — 4 k-rows per block, 64 blocks.
// ---------------------------------------------------------------------------
__global__ __launch_bounds__(128)
void prep_w4(const float* __restrict__ W_q, const float* __restrict__ W_off,
             const float* __restrict__ W_attn, float* __restrict__ W_aug)
{
    const int t = threadIdx.x;
    const int k0 = blockIdx.x * 4;
    __shared__ float a[4][256];
    for (int i = t; i < 1024; i += 128)
        a[i >> 8][i & 255] = W_q[(size_t)(k0 + (i >> 8)) * 256 + (i & 255)];
    __syncthreads();

    float s0 = 0.f, s1 = 0.f, s2 = 0.f, s3 = 0.f;
    if (t < 64) {
#pragma unroll 4
        for (int i = 0; i < 256; i++) {
            const float w = W_off[i * 64 + t];
            s0 = fmaf(a[0][i], w, s0); s1 = fmaf(a[1][i], w, s1);
            s2 = fmaf(a[2][i], w, s2); s3 = fmaf(a[3][i], w, s3);
        }
    } else if (t < 96) {
        const int j = t - 64;
#pragma unroll 4
        for (int i = 0; i < 256; i++) {
            const float w = W_attn[i * 32 + j];
            s0 = fmaf(a[0][i], w, s0); s1 = fmaf(a[1][i], w, s1);
            s2 = fmaf(a[2][i], w, s2); s3 = fmaf(a[3][i], w, s3);
        }
    }
    W_aug[(size_t)(k0 + 0) * 128 + t] = s0;
    W_aug[(size_t)(k0 + 1) * 128 + t] = s1;
    W_aug[(size_t)(k0 + 2) * 128 + t] = s2;
    W_aug[(size_t)(k0 + 3) * 128 + t] = s3;
}

__global__ void prep_bias(const float* __restrict__ b_q, const float* __restrict__ b_off,
                          const float* __restrict__ b_attn,
                          const float* __restrict__ W_off, const float* __restrict__ W_attn,
                          float* __restrict__ b_aug)
{
    const int n = threadIdx.x;   // 128
    float v = 0.f;
    if (n < 64) {
        float s = b_off[n];
        for (int i = 0; i < 256; i++) s = fmaf(b_q[i], W_off[i * 64 + n], s);
        v = s;
    } else if (n < 96) {
        const int j = n - 64;
        float s = b_attn[j];
        for (int i = 0; i < 256; i++) s = fmaf(b_q[i], W_attn[i * 32 + j], s);
        v = s;
    }
    b_aug[n] = v;
}

// b_fold = (b_do + b_q) @ W_out + b_out
__global__ void prep_bfold(const float* __restrict__ b_q, const float* __restrict__ b_do,
                           const float* __restrict__ b_out, const float* __restrict__ W_out,
                           float* __restrict__ bf)
{
    const int n = threadIdx.x;   // 256
    __shared__ float bs[256];
    bs[n] = b_do[n] + b_q[n];
    __syncthreads();
    float s = b_out[n];
#pragma unroll 8
    for (int k = 0; k < 256; k++) s = fmaf(bs[k], W_out[k * 256 + n], s);
    bf[n] = s;
}

// ---------------------------------------------------------------------------
// Weight fold: Wfold[0:256] = W_do@W_out ; [256:512] = W_q@W_out.
// 8 rows/block, 64 blocks -> W_out L2 traffic only 16 MB (contention-safe).
// ---------------------------------------------------------------------------
__global__ __launch_bounds__(256)
void fold8(const float* __restrict__ W_do, const float* __restrict__ W_q,
           const float* __restrict__ W_out, float* __restrict__ Wfold)
{
    const int t = threadIdx.x;
    const int r0 = blockIdx.x * 8;   // 0..504 over concat [W_do; W_q]
    __shared__ float a[8][256];
    for (int i = t; i < 2048; i += 256) {
        const int r = r0 + (i >> 8);
        const float* src = (r < 256) ? (W_do + (size_t)r * 256)
                                     : (W_q + (size_t)(r - 256) * 256);
        a[i >> 8][i & 255] = src[i & 255];
    }
    __syncthreads();

    float acc[8];
#pragma unroll
    for (int r = 0; r < 8; r++) acc[r] = 0.f;
#pragma unroll 4
    for (int k = 0; k < 256; k++) {
        const float w = W_out[(size_t)k * 256 + t];
#pragma unroll
        for (int r = 0; r < 8; r++) acc[r] = fmaf(a[r][k], w, acc[r]);
    }
#pragma unroll
    for (int r = 0; r < 8; r++)
        Wfold[(size_t)(r0 + r) * 256 + t] = acc[r];
}

// ---------------------------------------------------------------------------
// GEMM: C[M x N] = A[M x 256] @ W[256 x N] + bias.  BM=128, BN=64, BK=16.
// ---------------------------------------------------------------------------
__global__ __launch_bounds__(256)
void gemm_v2(const float* __restrict__ A, const float* __restrict__ W,
             const float* __restrict__ bias, float* __restrict__ C, int ldc, int ldw)
{
    __shared__ float As[16][132];
    __shared__ __align__(16) float Bs[16][64];

    const int tid = threadIdx.x;
    const int tx = tid & 15, ty = tid >> 4;
    const int n0 = blockIdx.x * 64;
    const int m0 = blockIdx.y * 128;

    float acc[8][4];
#pragma unroll
    for (int i = 0; i < 8; i++)
#pragma unroll
        for (int j = 0; j < 4; j++) acc[i][j] = 0.f;

    for (int k0 = 0; k0 < 256; k0 += 16) {
        {
            const int mr = tid >> 2;
            const int kq = (tid & 3) * 4;
#pragma unroll
            for (int r = 0; r < 2; r++) {
                const int m = mr + 64 * r;
                float4 v = *(const float4*)(A + (size_t)(m0 + m) * 256 + k0 + kq);
                As[kq + 0][m] = v.x; As[kq + 1][m] = v.y;
                As[kq + 2][m] = v.z; As[kq + 3][m] = v.w;
            }
        }
        {
            const int kr = tid >> 4;
            const int nq = (tid & 15) * 4;
            *(float4*)&Bs[kr][nq] = *(const float4*)(W + (size_t)(k0 + kr) * ldw + n0 + nq);
        }
        __syncthreads();

#pragma unroll
        for (int k = 0; k < 16; k++) {
            float a[8], b[4];
#pragma unroll
            for (int i = 0; i < 4; i++) {
                a[i]     = As[k][ty * 4 + i];
                a[i + 4] = As[k][64 + ty * 4 + i];
            }
#pragma unroll
            for (int j = 0; j < 4; j++) b[j] = Bs[k][tx * 4 + j];
#pragma unroll
            for (int i = 0; i < 8; i++)
#pragma unroll
                for (int j = 0; j < 4; j++)
                    acc[i][j] = fmaf(a[i], b[j], acc[i][j]);
        }
        __syncthreads();
    }

#pragma unroll
    for (int i = 0; i < 8; i++) {
        const int m = m0 + (i < 4 ? ty * 4 + i : 64 + ty * 4 + (i - 4));
#pragma unroll
        for (int j = 0; j < 4; j++) {
            const int n = n0 + tx * 4 + j;
            C[(size_t)m * ldc + n] = acc[i][j] + bias[n];
        }
    }
}

// ---------------------------------------------------------------------------
// Dual-A GEMM (K=512): C = [A1 | A2] @ W512 + bias. BM=128, BN=64 (R6 version).
// ---------------------------------------------------------------------------
__global__ __launch_bounds__(256)
void gemm_dual(const float* __restrict__ A1, const float* __restrict__ A2,
               const float* __restrict__ W, const float* __restrict__ bias,
               float* __restrict__ C)
{
    __shared__ float As[16][132];
    __shared__ __align__(16) float Bs[16][64];

    const int tid = threadIdx.x;
    const int tx = tid & 15, ty = tid >> 4;
    const int n0 = blockIdx.x * 64;
    const int m0 = blockIdx.y * 128;

    float acc[8][4];
#pragma unroll
    for (int i = 0; i < 8; i++)
#pragma unroll
        for (int j = 0; j < 4; j++) acc[i][j] = 0.f;

    for (int k0 = 0; k0 < 512; k0 += 16) {
        const float* A = (k0 < 256) ? A1 : A2;
        const int kk = k0 & 255;
        {
            const int mr = tid >> 2;
            const int kq = (tid & 3) * 4;
#pragma unroll
            for (int r = 0; r < 2; r++) {
                const int m = mr + 64 * r;
                float4 v = *(const float4*)(A + (size_t)(m0 + m) * 256 + kk + kq);
                As[kq + 0][m] = v.x; As[kq + 1][m] = v.y;
                As[kq + 2][m] = v.z; As[kq + 3][m] = v.w;
            }
        }
        {
            const int kr = tid >> 4;
            const int nq = (tid & 15) * 4;
            *(float4*)&Bs[kr][nq] = *(const float4*)(W + (size_t)(k0 + kr) * 256 + n0 + nq);
        }
        __syncthreads();

#pragma unroll
        for (int k = 0; k < 16; k++) {
            float a[8], b[4];
#pragma unroll
            for (int i = 0; i < 4; i++) {
                a[i]     = As[k][ty * 4 + i];
                a[i + 4] = As[k][64 + ty * 4 + i];
            }
#pragma unroll
            for (int j = 0; j < 4; j++) b[j] = Bs[k][tx * 4 + j];
#pragma unroll
            for (int i = 0; i < 8; i++)
#pragma unroll
                for (int j = 0; j < 4; j++)
                    acc[i][j] = fmaf(a[i], b[j], acc[i][j]);
        }
        __syncthreads();
    }

#pragma unroll
    for (int i = 0; i < 8; i++) {
        const int m = m0 + (i < 4 ? ty * 4 + i : 64 + ty * 4 + (i - 4));
#pragma unroll
        for (int j = 0; j < 4; j++) {
            const int n = n0 + tx * 4 + j;
            C[(size_t)m * 256 + n] = acc[i][j] + bias[n];
        }
    }
}

// ---------------------------------------------------------------------------
// Monolithic transpose bev [B, C=256, HW] -> bevTh [B, HW, C] in fp16.
// ---------------------------------------------------------------------------
__global__ __launch_bounds__(256)
void transpose_h(const float* __restrict__ src, __half* __restrict__ dst)
{
    __shared__ float tile[32 * 65];
    const int b  = blockIdx.z;
    const int p0 = blockIdx.x * 64;
    const int c0 = blockIdx.y * 32;
    const int tid = threadIdx.x;

#pragma unroll
    for (int l = 0; l < 2; l++) {
        const int c = l * 16 + (tid >> 4);
        const int p = (tid & 15) * 4;
        float4 v = *(const float4*)(src + ((size_t)(b * 256 + c0 + c)) * NHW + p0 + p);
        tile[c * 65 + p + 0] = v.x;
        tile[c * 65 + p + 1] = v.y;
        tile[c * 65 + p + 2] = v.z;
        tile[c * 65 + p + 3] = v.w;
    }
    __syncthreads();

#pragma unroll
    for (int l = 0; l < 2; l++) {
        const int p  = l * 32 + (tid >> 3);
        const int cq = (tid & 7) * 4;
        const __half2 h01 = __floats2half2_rn(tile[(cq + 0) * 65 + p], tile[(cq + 1) * 65 + p]);
        const __half2 h23 = __floats2half2_rn(tile[(cq + 2) * 65 + p], tile[(cq + 3) * 65 + p]);
        uint2 u;
        u.x = *reinterpret_cast<const unsigned*>(&h01);
        u.y = *reinterpret_cast<const unsigned*>(&h23);
        *(uint2*)(dst + ((size_t)b * NHW + p0 + p) * 256 + c0 + cq) = u;
    }
}

// ---------------------------------------------------------------------------
// Gather with pixel dedup over fp16 bevT. Block per row (R6 structure).
// ---------------------------------------------------------------------------
__global__ __launch_bounds__(256)
void gather_kernel(const float* __restrict__ ctrl, const float* __restrict__ pcr,
                   const __half* __restrict__ bevT, const float* __restrict__ qoa,
                   float* __restrict__ g, float* __restrict__ wsum)
{
    const int row = blockIdx.x;
    const int b = row >> 10;
    const int t = threadIdx.x;

    __shared__ int    s_idx[128];
    __shared__ float  s_w[128];
    __shared__ float  ws[32];
    __shared__ int    hidx[256];
    __shared__ float  hw[256][8];
    __shared__ int    slots[128];
    __shared__ int    cnt;
    __shared__ float4 red4[4 * 8 * 64];   // 32KB

    hidx[t] = -1;
    {
        float* hwf = &hw[0][0];
#pragma unroll
        for (int i = 0; i < 8; i++) hwf[t + 256 * i] = 0.f;
    }
    if (t == 0) cnt = 0;

    if (t < 32) {
        const float lox = pcr[0], loy = pcr[1];
        const float spx = pcr[3] - pcr[0], spy = pcr[4] - pcr[1];
        const float* cp = ctrl + (size_t)row * 8;
        const float c0x = cp[0], c0y = cp[1], c1x = cp[2], c1y = cp[3];
        const float c2x = cp[4], c2y = cp[5], c3x = cp[6], c3y = cp[7];
        float sx = 0.f, sy = 0.f;
#pragma unroll
        for (int k = 0; k < 10; k++) {
            const float tt = (float)k / 9.0f;
            const float u = 1.0f - tt;
            const float w0 = u*u*u, w1 = 3.f*u*u*tt, w2 = 3.f*u*tt*tt, w3 = tt*tt*tt;
            const float dx = w0*c0x + w1*c1x + w2*c2x + w3*c3x;
            const float dy = w0*c0y + w1*c1y + w2*c2y + w3*c3y;
            sx += fminf(fmaxf((dx - lox) / spx, 0.01f), 0.99f);
            sy += fminf(fmaxf((dy - loy) / spy, 0.01f), 0.99f);
        }
        const float rcx = sx * 0.1f, rcy = sy * 0.1f;

        const int h = t >> 2, p = t & 3;
        const float* lg = qoa + (size_t)row * NAUG + 64 + h * 4;
        const float l0 = lg[0], l1 = lg[1], l2 = lg[2], l3 = lg[3];
        const float m = fmaxf(fmaxf(l0, l1), fmaxf(l2, l3));
        const float e0 = expf(l0 - m), e1 = expf(l1 - m), e2 = expf(l2 - m), e3 = expf(l3 - m);
        const float lp = (p == 0) ? l0 : (p == 1) ? l1 : (p == 2) ? l2 : l3;
        const float aw = expf(lp - m) / (e0 + e1 + e2 + e3);

        const float ox = qoa[(size_t)row * NAUG + h * 8 + p * 2 + 0];
        const float oy = qoa[(size_t)row * NAUG + h * 8 + p * 2 + 1];
        const float x = (rcx + ox / (float)GW) * (float)GW - 0.5f;
        const float y = (rcy + oy / (float)GH) * (float)GH - 0.5f;
        const float fx = floorf(x), fy = floorf(y);
        const int x0 = (int)fx, y0 = (int)fy;
        const int x1 = x0 + 1,  y1 = y0 + 1;
        const float wx = x - fx, wy = y - fy;
        const bool vx0 = (x0 >= 0) & (x0 < GW), vx1 = (x1 >= 0) & (x1 < GW);
        const bool vy0 = (y0 >= 0) & (y0 < GH), vy1 = (y1 >= 0) & (y1 < GH);
        const int cx0 = min(max(x0, 0), GW - 1), cx1 = min(max(x1, 0), GW - 1);
        const int cy0 = min(max(y0, 0), GH - 1), cy1 = min(max(y1, 0), GH - 1);
        const float w00 = (vy0 & vx0) ? (1.f - wx) * (1.f - wy) * aw : 0.f;
        const float w01 = (vy0 & vx1) ? wx * (1.f - wy) * aw : 0.f;
        const float w10 = (vy1 & vx0) ? (1.f - wx) * wy * aw : 0.f;
        const float w11 = (vy1 & vx1) ? wx * wy * aw : 0.f;
        s_idx[t*4+0] = cy0 * GW + cx0;  s_w[t*4+0] = w00;
        s_idx[t*4+1] = cy0 * GW + cx1;  s_w[t*4+1] = w01;
        s_idx[t*4+2] = cy1 * GW + cx0;  s_w[t*4+2] = w10;
        s_idx[t*4+3] = cy1 * GW + cx1;  s_w[t*4+3] = w11;
        ws[t] = w00 + w01 + w10 + w11;
    }
    __syncthreads();

    if (t < 128) {
        const int idx = s_idx[t];
        const float w = s_w[t];
        const int h = t >> 4;
        unsigned s = ((unsigned)idx * 2654435761u) >> 24;
        while (true) {
            int prev = atomicCAS(&hidx[s], -1, idx);
            if (prev == -1 || prev == idx) { atomicAdd(&hw[s][h], w); break; }
            s = (s + 1) & 255;
        }
    }
    __syncthreads();

    if (hidx[t] >= 0) {
        const int p = atomicAdd(&cnt, 1);
        slots[p] = t;
    }
    __syncthreads();

    const int cq = t & 63;
    const int stripe = t >> 6;
    float4 acc8[8];
#pragma unroll
    for (int h = 0; h < 8; h++) acc8[h] = make_float4(0.f, 0.f, 0.f, 0.f);

    const int n = cnt;
    const __half* basep = bevT + ((size_t)b * NHW) * 256 + cq * 4;

    for (int i = stripe; i < n; i += 4) {
        const int slot = slots[i];
        const uint2 raw = *(const uint2*)(basep + (size_t)hidx[slot] * 256);
        const float2 f01 = __half22float2(*reinterpret_cast<const __half2*>(&raw.x));
        const float2 f23 = __half22float2(*reinterpret_cast<const __half2*>(&raw.y));
#pragma unroll
        for (int h = 0; h < 8; h++) {
            const float w = hw[slot][h];
            acc8[h].x = fmaf(w, f01.x, acc8[h].x);
            acc8[h].y = fmaf(w, f01.y, acc8[h].y);
            acc8[h].z = fmaf(w, f23.x, acc8[h].z);
            acc8[h].w = fmaf(w, f23.y, acc8[h].w);
        }
    }
#pragma unroll
    for (int h = 0; h < 8; h++)
        red4[(stripe * 8 + h) * 64 + cq] = acc8[h];
    __syncthreads();

#pragma unroll
    for (int j = 0; j < 2; j++) {
        const int pos = t + j * 256;
        const int h = pos >> 6, q = pos & 63;
        float4 a = red4[(0 * 8 + h) * 64 + q];
        const float4 b1 = red4[(1 * 8 + h) * 64 + q];
        const float4 b2 = red4[(2 * 8 + h) * 64 + q];
        const float4 b3 = red4[(3 * 8 + h) * 64 + q];
        a.x += b1.x + b2.x + b3.x;
        a.y += b1.y + b2.y + b3.y;
        a.z += b1.z + b2.z + b3.z;
        a.w += b1.w + b2.w + b3.w;
        *(float4*)(g + ((size_t)row * 8 + h) * 256 + q * 4) = a;
    }

    if (t < 8)
        wsum[(size_t)row * 8 + t] = ws[t*4] + ws[t*4+1] + ws[t*4+2] + ws[t*4+3];
}

// ---------------------------------------------------------------------------
// Block-diagonal projection.
// ---------------------------------------------------------------------------
__global__ __launch_bounds__(256)
void proj_kernel(const float* __restrict__ g, const float* __restrict__ wsum,
                 const float* __restrict__ W_val, const float* __restrict__ b_val,
                 float* __restrict__ samp)
{
    const int h  = blockIdx.y;
    const int r0 = blockIdx.x * 128;
    const int t  = threadIdx.x;
    const int d = t & 31, rg = t >> 5;

    __shared__ float Ws[256 * 32];
    __shared__ float As[128 * 36];

#pragma unroll
    for (int i = 0; i < 32; i++) {
        const int k = i * 8 + (t >> 5);
        Ws[k * 32 + d] = W_val[(size_t)k * 256 + h * 32 + d];
    }
    const float bv = b_val[h * 32 + d];

    float acc[16];
#pragma unroll
    for (int r = 0; r < 16; r++) acc[r] = 0.f;

    for (int kt = 0; kt < 8; kt++) {
        __syncthreads();
        {
            const int i = t >> 1, half = t & 1;
            const float* src = g + ((size_t)(r0 + i) * 8 + h) * 256 + kt * 32 + half * 16;
            float* dst = &As[i * 36 + half * 16];
#pragma unroll
            for (int q = 0; q < 4; q++)
                *(float4*)(dst + q * 4) = *(const float4*)(src + q * 4);
        }
        __syncthreads();

#pragma unroll
        for (int k = 0; k < 32; k++) {
            const float wv = Ws[(kt * 32 + k) * 32 + d];
#pragma unroll
            for (int r = 0; r < 16; r++)
                acc[r] = fmaf(As[(rg * 16 + r) * 36 + k], wv, acc[r]);
        }
    }

#pragma unroll
    for (int r = 0; r < 16; r++) {
        const int row = r0 + rg * 16 + r;
        samp[(size_t)row * 256 + h * 32 + d] = acc[r] + wsum[(size_t)row * 8 + h] * bv;
    }
}

// ---------------------------------------------------------------------------
extern "C" void kernel_launch(void* const* d_in, const int* in_sizes, int n_in,
                              void* d_out, int out_size)
{
    const float* query_embed = (const float*)d_in[0];
    const float* ctrl        = (const float*)d_in[1];
    const float* bev         = (const float*)d_in[2];
    /* d_in[3] spatial_shapes unused */
    const float* pc_range    = (const float*)d_in[4];
    const float* W_q   = (const float*)d_in[5];
    const float* b_q   = (const float*)d_in[6];
    const float* W_val = (const float*)d_in[7];
    const float* b_val = (const float*)d_in[8];
    const float* W_off = (const float*)d_in[9];
    const float* b_off = (const float*)d_in[10];
    const float* W_attn = (const float*)d_in[11];
    const float* b_attn = (const float*)d_in[12];
    const float* W_do  = (const float*)d_in[13];
    const float* b_do  = (const float*)d_in[14];
    const float* W_out = (const float*)d_in[15];
    const float* b_out = (const float*)d_in[16];
    float* out = (float*)d_out;

    float *pqoa, *pWaug, *pbaug, *pWfold, *pbfold, *pg, *pws, *ps;
    __half *pbTh;
    cudaGetSymbolAddress((void**)&pqoa,  g_qoa);
    cudaGetSymbolAddress((void**)&pWaug, g_Waug);
    cudaGetSymbolAddress((void**)&pbaug, g_baug);
    cudaGetSymbolAddress((void**)&pWfold, g_Wfold);
    cudaGetSymbolAddress((void**)&pbfold, g_bfold);
    cudaGetSymbolAddress((void**)&pg,    g_gath);
    cudaGetSymbolAddress((void**)&pws,   g_wsum);
    cudaGetSymbolAddress((void**)&pbTh,  g_bevTh);
    cudaGetSymbolAddress((void**)&ps,    g_samp);

    static cudaStream_t s1 = nullptr, s2 = nullptr;
    static cudaEvent_t evFork = nullptr, evT = nullptr, evS2 = nullptr;
    if (s1 == nullptr) {
        cudaStreamCreateWithFlags(&s1, cudaStreamNonBlocking);
        cudaStreamCreateWithFlags(&s2, cudaStreamNonBlocking);
        cudaEventCreateWithFlags(&evFork, cudaEventDisableTiming);
        cudaEventCreateWithFlags(&evT,    cudaEventDisableTiming);
        cudaEventCreateWithFlags(&evS2,   cudaEventDisableTiming);
    }

    cudaEventRecord(evFork, 0);
    cudaStreamWaitEvent(s1, evFork, 0);
    cudaStreamWaitEvent(s2, evFork, 0);

    // s1: monolithic DRAM-bound transpose (fp16 output)
    transpose_h<<<dim3(NHW / 64, DIM / 32, NB), 256, 0, s1>>>(bev, pbTh);
    cudaEventRecord(evT, s1);

    // s2: contention-free weight/bias folds
    prep_bfold<<<1, 256, 0, s2>>>(b_q, b_do, b_out, W_out, pbfold);
    fold8<<<64, 256, 0, s2>>>(W_do, W_q, W_out, pWfold);
    cudaEventRecord(evS2, s2);

    // main: offsets/logits path
    prep_w4<<<64, 128>>>(W_q, W_off, W_attn, pWaug);
    prep_bias<<<1, NAUG>>>(b_q, b_off, b_attn, W_off, W_attn, pbaug);
    gemm_v2<<<dim3(NAUG / 64, NROWS / 128), 256>>>(
        query_embed, pWaug, pbaug, pqoa, NAUG, NAUG);

    cudaStreamWaitEvent(0, evT, 0);

    // gather (dedup, fp16 features) + per-head projection
    gather_kernel<<<NROWS, 256>>>(ctrl, pc_range, pbTh, pqoa, pg, pws);
    proj_kernel<<<dim3(NROWS / 128, NHEADS), 256>>>(pg, pws, W_val, b_val, ps);

    cudaStreamWaitEvent(0, evS2, 0);

    // out = samp@(W_do W_out) + qe@(W_q W_out) + b_fold
    gemm_dual<<<dim3(DIM / 64, NROWS / 128), 256>>>(
        ps, query_embed, pWfold, pbfold, out);
}

// round 10
// speedup vs baseline: 1.2762x; 1.0650x over previous
#include <cuda_runtime.h>
#include <cuda_fp16.h>
#include <math.h>

#define NB     4
#define NQ     1024
#define DIM    256
#define NHEADS 8
#define GH     200
#define GW     200
#define NHW    (GH*GW)       // 40000
#define NROWS  (NB*NQ)       // 4096
#define NAUG   128           // 64 off | 32 attn logits | 32 pad

// Scratch (__device__ globals: allocation-free per harness rules)
__device__ float  g_qoa  [NROWS * NAUG];
__device__ float  g_Waug [DIM * NAUG];
__device__ float  g_baug [NAUG];
__device__ float  g_Wfold[512 * DIM];                     // [W_do@W_out ; W_q@W_out]
__device__ float  g_bfold[DIM];
__device__ float  g_gath [(size_t)NROWS * NHEADS * DIM];  // 32 MB
__device__ float  g_wsum [NROWS * NHEADS];
__device__ __half g_bevTh[(size_t)NB * NHW * DIM];        // 82 MB fp16 [B, HW, C]
__device__ float  g_samp [NROWS * DIM];

// ---------------------------------------------------------------------------
// prep_w: one block per k-row (257 blocks; row 256 = bias).
// W_aug[k][0:64]=W_q[k]·W_off, [64:96]=W_q[k]·W_attn; b_aug analogous.
// ---------------------------------------------------------------------------
__global__ __launch_bounds__(128)
void prep_w(const float* __restrict__ W_q, const float* __restrict__ W_off,
            const float* __restrict__ W_attn,
            const float* __restrict__ b_q, const float* __restrict__ b_off,
            const float* __restrict__ b_attn,
            float* __restrict__ W_aug, float* __restrict__ b_aug)
{
    const int k = blockIdx.x;     // 0..256
    const int t = threadIdx.x;    // 0..127
    __shared__ float a[256];
    const float* src = (k < 256) ? (W_q + (size_t)k * 256) : b_q;
    a[t] = src[t];
    a[t + 128] = src[t + 128];
    __syncthreads();

    float v = 0.f;
    if (t < 64) {
#pragma unroll 8
        for (int i = 0; i < 256; i++) v = fmaf(a[i], W_off[i * 64 + t], v);
        if (k == 256) v += b_off[t];
    } else if (t < 96) {
        const int j = t - 64;
#pragma unroll 8
        for (int i = 0; i < 256; i++) v = fmaf(a[i], W_attn[i * 32 + j], v);
        if (k == 256) v += b_attn[j];
    }
    if (k < 256) W_aug[(size_t)k * 128 + t] = v;
    else         b_aug[t] = v;
}

// b_fold = (b_do + b_q) @ W_out + b_out
__global__ void prep_bfold(const float* __restrict__ b_q, const float* __restrict__ b_do,
                           const float* __restrict__ b_out, const float* __restrict__ W_out,
                           float* __restrict__ bf)
{
    const int n = threadIdx.x;   // 256
    __shared__ float bs[256];
    bs[n] = b_do[n] + b_q[n];
    __syncthreads();
    float s = b_out[n];
#pragma unroll 8
    for (int k = 0; k < 256; k++) s = fmaf(bs[k], W_out[k * 256 + n], s);
    bf[n] = s;
}

// ---------------------------------------------------------------------------
// fold8: Wfold[0:256]=W_do@W_out ; [256:512]=W_q@W_out. 64 blocks, 8 rows each.
// ---------------------------------------------------------------------------
__global__ __launch_bounds__(256)
void fold8(const float* __restrict__ W_do, const float* __restrict__ W_q,
           const float* __restrict__ W_out, float* __restrict__ Wfold)
{
    const int t = threadIdx.x;
    const int r0 = blockIdx.x * 8;
    __shared__ float a[8][256];
    for (int i = t; i < 2048; i += 256) {
        const int r = r0 + (i >> 8);
        const float* src = (r < 256) ? (W_do + (size_t)r * 256)
                                     : (W_q + (size_t)(r - 256) * 256);
        a[i >> 8][i & 255] = src[i & 255];
    }
    __syncthreads();

    float acc[8];
#pragma unroll
    for (int r = 0; r < 8; r++) acc[r] = 0.f;
#pragma unroll 4
    for (int k = 0; k < 256; k++) {
        const float w = W_out[(size_t)k * 256 + t];
#pragma unroll
        for (int r = 0; r < 8; r++) acc[r] = fmaf(a[r][k], w, acc[r]);
    }
#pragma unroll
    for (int r = 0; r < 8; r++)
        Wfold[(size_t)(r0 + r) * 256 + t] = acc[r];
}

// ---------------------------------------------------------------------------
// qoa GEMM: C[4096 x 128] = A[4096 x 256] @ W[256 x 128] + bias.
// BM=64, BN=64, BK=16, 256 threads, 4x4 microtile. grid (2, 64) = 128 blocks.
// ---------------------------------------------------------------------------
__global__ __launch_bounds__(256)
void gemm_qoa(const float* __restrict__ A, const float* __restrict__ W,
              const float* __restrict__ bias, float* __restrict__ C)
{
    __shared__ float As[16][68];
    __shared__ __align__(16) float Bs[16][64];

    const int tid = threadIdx.x;
    const int tx = tid & 15, ty = tid >> 4;
    const int n0 = blockIdx.x * 64;
    const int m0 = blockIdx.y * 64;

    float acc[4][4];
#pragma unroll
    for (int i = 0; i < 4; i++)
#pragma unroll
        for (int j = 0; j < 4; j++) acc[i][j] = 0.f;

    for (int k0 = 0; k0 < 256; k0 += 16) {
        {
            const int m = tid >> 2;
            const int kq = (tid & 3) * 4;
            float4 v = *(const float4*)(A + (size_t)(m0 + m) * 256 + k0 + kq);
            As[kq + 0][m] = v.x; As[kq + 1][m] = v.y;
            As[kq + 2][m] = v.z; As[kq + 3][m] = v.w;
        }
        {
            const int kr = tid >> 4;
            const int nq = (tid & 15) * 4;
            *(float4*)&Bs[kr][nq] = *(const float4*)(W + (size_t)(k0 + kr) * 128 + n0 + nq);
        }
        __syncthreads();

#pragma unroll
        for (int k = 0; k < 16; k++) {
            float a[4], b[4];
#pragma unroll
            for (int i = 0; i < 4; i++) a[i] = As[k][ty * 4 + i];
#pragma unroll
            for (int j = 0; j < 4; j++) b[j] = Bs[k][tx * 4 + j];
#pragma unroll
            for (int i = 0; i < 4; i++)
#pragma unroll
                for (int j = 0; j < 4; j++)
                    acc[i][j] = fmaf(a[i], b[j], acc[i][j]);
        }
        __syncthreads();
    }

#pragma unroll
    for (int i = 0; i < 4; i++) {
        const int m = m0 + ty * 4 + i;
#pragma unroll
        for (int j = 0; j < 4; j++) {
            const int n = n0 + tx * 4 + j;
            C[(size_t)m * 128 + n] = acc[i][j] + bias[n];
        }
    }
}

// ---------------------------------------------------------------------------
// Dual-A GEMM (K=512): C = [A1 | A2] @ W512 + bias. BM=64, BN=64, 256 blocks.
// ---------------------------------------------------------------------------
__global__ __launch_bounds__(256)
void gemm_dual64(const float* __restrict__ A1, const float* __restrict__ A2,
                 const float* __restrict__ W, const float* __restrict__ bias,
                 float* __restrict__ C)
{
    __shared__ float As[16][68];
    __shared__ __align__(16) float Bs[16][64];

    const int tid = threadIdx.x;
    const int tx = tid & 15, ty = tid >> 4;
    const int n0 = blockIdx.x * 64;
    const int m0 = blockIdx.y * 64;

    float acc[4][4];
#pragma unroll
    for (int i = 0; i < 4; i++)
#pragma unroll
        for (int j = 0; j < 4; j++) acc[i][j] = 0.f;

    for (int k0 = 0; k0 < 512; k0 += 16) {
        const float* A = (k0 < 256) ? A1 : A2;
        const int kk = k0 & 255;
        {
            const int m = tid >> 2;
            const int kq = (tid & 3) * 4;
            float4 v = *(const float4*)(A + (size_t)(m0 + m) * 256 + kk + kq);
            As[kq + 0][m] = v.x; As[kq + 1][m] = v.y;
            As[kq + 2][m] = v.z; As[kq + 3][m] = v.w;
        }
        {
            const int kr = tid >> 4;
            const int nq = (tid & 15) * 4;
            *(float4*)&Bs[kr][nq] = *(const float4*)(W + (size_t)(k0 + kr) * 256 + n0 + nq);
        }
        __syncthreads();

#pragma unroll
        for (int k = 0; k < 16; k++) {
            float a[4], b[4];
#pragma unroll
            for (int i = 0; i < 4; i++) a[i] = As[k][ty * 4 + i];
#pragma unroll
            for (int j = 0; j < 4; j++) b[j] = Bs[k][tx * 4 + j];
#pragma unroll
            for (int i = 0; i < 4; i++)
#pragma unroll
                for (int j = 0; j < 4; j++)
                    acc[i][j] = fmaf(a[i], b[j], acc[i][j]);
        }
        __syncthreads();
    }

#pragma unroll
    for (int i = 0; i < 4; i++) {
        const int m = m0 + ty * 4 + i;
#pragma unroll
        for (int j = 0; j < 4; j++) {
            const int n = n0 + tx * 4 + j;
            C[(size_t)m * 256 + n] = acc[i][j] + bias[n];
        }
    }
}

// ---------------------------------------------------------------------------
// Monolithic transpose bev [B, C=256, HW] -> bevTh [B, HW, C] in fp16.
// ---------------------------------------------------------------------------
__global__ __launch_bounds__(256)
void transpose_h(const float* __restrict__ src, __half* __restrict__ dst)
{
    __shared__ float tile[32 * 65];
    const int b  = blockIdx.z;
    const int p0 = blockIdx.x * 64;
    const int c0 = blockIdx.y * 32;
    const int tid = threadIdx.x;

#pragma unroll
    for (int l = 0; l < 2; l++) {
        const int c = l * 16 + (tid >> 4);
        const int p = (tid & 15) * 4;
        float4 v = *(const float4*)(src + ((size_t)(b * 256 + c0 + c)) * NHW + p0 + p);
        tile[c * 65 + p + 0] = v.x;
        tile[c * 65 + p + 1] = v.y;
        tile[c * 65 + p + 2] = v.z;
        tile[c * 65 + p + 3] = v.w;
    }
    __syncthreads();

#pragma unroll
    for (int l = 0; l < 2; l++) {
        const int p  = l * 32 + (tid >> 3);
        const int cq = (tid & 7) * 4;
        const __half2 h01 = __floats2half2_rn(tile[(cq + 0) * 65 + p], tile[(cq + 1) * 65 + p]);
        const __half2 h23 = __floats2half2_rn(tile[(cq + 2) * 65 + p], tile[(cq + 3) * 65 + p]);
        uint2 u;
        u.x = *reinterpret_cast<const unsigned*>(&h01);
        u.y = *reinterpret_cast<const unsigned*>(&h23);
        *(uint2*)(dst + ((size_t)b * NHW + p0 + p) * 256 + c0 + cq) = u;
    }
}

// ---------------------------------------------------------------------------
// Gather with pixel dedup (fp16 features). Block per row.
// smem cut to ~28 KB via two-round stripe reduction -> 8 blocks/SM.
// ---------------------------------------------------------------------------
__global__ __launch_bounds__(256)
void gather_kernel(const float* __restrict__ ctrl, const float* __restrict__ pcr,
                   const __half* __restrict__ bevT, const float* __restrict__ qoa,
                   float* __restrict__ g, float* __restrict__ wsum)
{
    const int row = blockIdx.x;
    const int b = row >> 10;
    const int t = threadIdx.x;

    __shared__ int    s_idx[128];
    __shared__ float  s_w[128];
    __shared__ float  ws[32];
    __shared__ int    hidx[256];
    __shared__ float  hw[256][8];
    __shared__ int    slots[128];
    __shared__ int    cnt;
    __shared__ float4 red[2 * 8 * 64];   // 16 KB (two-round reduction buffer)

    hidx[t] = -1;
    {
        float* hwf = &hw[0][0];
#pragma unroll
        for (int i = 0; i < 8; i++) hwf[t + 256 * i] = 0.f;
    }
    if (t == 0) cnt = 0;

    if (t < 32) {
        const float lox = pcr[0], loy = pcr[1];
        const float spx = pcr[3] - pcr[0], spy = pcr[4] - pcr[1];
        const float* cp = ctrl + (size_t)row * 8;
        const float c0x = cp[0], c0y = cp[1], c1x = cp[2], c1y = cp[3];
        const float c2x = cp[4], c2y = cp[5], c3x = cp[6], c3y = cp[7];
        float sx = 0.f, sy = 0.f;
#pragma unroll
        for (int k = 0; k < 10; k++) {
            const float tt = (float)k / 9.0f;
            const float u = 1.0f - tt;
            const float w0 = u*u*u, w1 = 3.f*u*u*tt, w2 = 3.f*u*tt*tt, w3 = tt*tt*tt;
            const float dx = w0*c0x + w1*c1x + w2*c2x + w3*c3x;
            const float dy = w0*c0y + w1*c1y + w2*c2y + w3*c3y;
            sx += fminf(fmaxf((dx - lox) / spx, 0.01f), 0.99f);
            sy += fminf(fmaxf((dy - loy) / spy, 0.01f), 0.99f);
        }
        const float rcx = sx * 0.1f, rcy = sy * 0.1f;

        const int h = t >> 2, p = t & 3;
        const float* lg = qoa + (size_t)row * NAUG + 64 + h * 4;
        const float l0 = lg[0], l1 = lg[1], l2 = lg[2], l3 = lg[3];
        const float m = fmaxf(fmaxf(l0, l1), fmaxf(l2, l3));
        const float e0 = expf(l0 - m), e1 = expf(l1 - m), e2 = expf(l2 - m), e3 = expf(l3 - m);
        const float lp = (p == 0) ? l0 : (p == 1) ? l1 : (p == 2) ? l2 : l3;
        const float aw = expf(lp - m) / (e0 + e1 + e2 + e3);

        const float ox = qoa[(size_t)row * NAUG + h * 8 + p * 2 + 0];
        const float oy = qoa[(size_t)row * NAUG + h * 8 + p * 2 + 1];
        const float x = (rcx + ox / (float)GW) * (float)GW - 0.5f;
        const float y = (rcy + oy / (float)GH) * (float)GH - 0.5f;
        const float fx = floorf(x), fy = floorf(y);
        const int x0 = (int)fx, y0 = (int)fy;
        const int x1 = x0 + 1,  y1 = y0 + 1;
        const float wx = x - fx, wy = y - fy;
        const bool vx0 = (x0 >= 0) & (x0 < GW), vx1 = (x1 >= 0) & (x1 < GW);
        const bool vy0 = (y0 >= 0) & (y0 < GH), vy1 = (y1 >= 0) & (y1 < GH);
        const int cx0 = min(max(x0, 0), GW - 1), cx1 = min(max(x1, 0), GW - 1);
        const int cy0 = min(max(y0, 0), GH - 1), cy1 = min(max(y1, 0), GH - 1);
        const float w00 = (vy0 & vx0) ? (1.f - wx) * (1.f - wy) * aw : 0.f;
        const float w01 = (vy0 & vx1) ? wx * (1.f - wy) * aw : 0.f;
        const float w10 = (vy1 & vx0) ? (1.f - wx) * wy * aw : 0.f;
        const float w11 = (vy1 & vx1) ? wx * wy * aw : 0.f;
        s_idx[t*4+0] = cy0 * GW + cx0;  s_w[t*4+0] = w00;
        s_idx[t*4+1] = cy0 * GW + cx1;  s_w[t*4+1] = w01;
        s_idx[t*4+2] = cy1 * GW + cx0;  s_w[t*4+2] = w10;
        s_idx[t*4+3] = cy1 * GW + cx1;  s_w[t*4+3] = w11;
        ws[t] = w00 + w01 + w10 + w11;
    }
    __syncthreads();

    if (t < 128) {
        const int idx = s_idx[t];
        const float w = s_w[t];
        const int h = t >> 4;
        unsigned s = ((unsigned)idx * 2654435761u) >> 24;
        while (true) {
            int prev = atomicCAS(&hidx[s], -1, idx);
            if (prev == -1 || prev == idx) { atomicAdd(&hw[s][h], w); break; }
            s = (s + 1) & 255;
        }
    }
    __syncthreads();

    if (hidx[t] >= 0) {
        const int p = atomicAdd(&cnt, 1);
        slots[p] = t;
    }
    __syncthreads();

    const int cq = t & 63;        // channel quad
    const int stripe = t >> 6;    // 0..3
    float4 acc8[8];
#pragma unroll
    for (int h = 0; h < 8; h++) acc8[h] = make_float4(0.f, 0.f, 0.f, 0.f);

    const int n = cnt;
    const __half* basep = bevT + ((size_t)b * NHW) * 256 + cq * 4;

    for (int i = stripe; i < n; i += 4) {
        const int slot = slots[i];
        const uint2 raw = *(const uint2*)(basep + (size_t)hidx[slot] * 256);
        const float2 f01 = __half22float2(*reinterpret_cast<const __half2*>(&raw.x));
        const float2 f23 = __half22float2(*reinterpret_cast<const __half2*>(&raw.y));
#pragma unroll
        for (int h = 0; h < 8; h++) {
            const float w = hw[slot][h];
            acc8[h].x = fmaf(w, f01.x, acc8[h].x);
            acc8[h].y = fmaf(w, f01.y, acc8[h].y);
            acc8[h].z = fmaf(w, f23.x, acc8[h].z);
            acc8[h].w = fmaf(w, f23.y, acc8[h].w);
        }
    }

    // Round 1: stripes 2,3 -> smem; stripes 0,1 accumulate.
    if (stripe >= 2) {
#pragma unroll
        for (int h = 0; h < 8; h++)
            red[((stripe - 2) * 8 + h) * 64 + cq] = acc8[h];
    }
    __syncthreads();
    if (stripe < 2) {
#pragma unroll
        for (int h = 0; h < 8; h++) {
            const float4 v = red[(stripe * 8 + h) * 64 + cq];
            acc8[h].x += v.x; acc8[h].y += v.y; acc8[h].z += v.z; acc8[h].w += v.w;
        }
    }
    __syncthreads();
    // Round 2: stripe 1 -> smem; stripe 0 adds and writes out.
    if (stripe == 1) {
#pragma unroll
        for (int h = 0; h < 8; h++)
            red[h * 64 + cq] = acc8[h];
    }
    __syncthreads();
    if (stripe == 0) {
#pragma unroll
        for (int h = 0; h < 8; h++) {
            const float4 v = red[h * 64 + cq];
            acc8[h].x += v.x; acc8[h].y += v.y; acc8[h].z += v.z; acc8[h].w += v.w;
            *(float4*)(g + ((size_t)row * 8 + h) * 256 + cq * 4) = acc8[h];
        }
    }

    if (t < 8)
        wsum[(size_t)row * 8 + t] = ws[t*4] + ws[t*4+1] + ws[t*4+2] + ws[t*4+3];
}

// ---------------------------------------------------------------------------
// Block-diagonal projection.
// ---------------------------------------------------------------------------
__global__ __launch_bounds__(256)
void proj_kernel(const float* __restrict__ g, const float* __restrict__ wsum,
                 const float* __restrict__ W_val, const float* __restrict__ b_val,
                 float* __restrict__ samp)
{
    const int h  = blockIdx.y;
    const int r0 = blockIdx.x * 128;
    const int t  = threadIdx.x;
    const int d = t & 31, rg = t >> 5;

    __shared__ float Ws[256 * 32];
    __shared__ float As[128 * 36];

#pragma unroll
    for (int i = 0; i < 32; i++) {
        const int k = i * 8 + (t >> 5);
        Ws[k * 32 + d] = W_val[(size_t)k * 256 + h * 32 + d];
    }
    const float bv = b_val[h * 32 + d];

    float acc[16];
#pragma unroll
    for (int r = 0; r < 16; r++) acc[r] = 0.f;

    for (int kt = 0; kt < 8; kt++) {
        __syncthreads();
        {
            const int i = t >> 1, half = t & 1;
            const float* src = g + ((size_t)(r0 + i) * 8 + h) * 256 + kt * 32 + half * 16;
            float* dst = &As[i * 36 + half * 16];
#pragma unroll
            for (int q = 0; q < 4; q++)
                *(float4*)(dst + q * 4) = *(const float4*)(src + q * 4);
        }
        __syncthreads();

#pragma unroll
        for (int k = 0; k < 32; k++) {
            const float wv = Ws[(kt * 32 + k) * 32 + d];
#pragma unroll
            for (int r = 0; r < 16; r++)
                acc[r] = fmaf(As[(rg * 16 + r) * 36 + k], wv, acc[r]);
        }
    }

#pragma unroll
    for (int r = 0; r < 16; r++) {
        const int row = r0 + rg * 16 + r;
        samp[(size_t)row * 256 + h * 32 + d] = acc[r] + wsum[(size_t)row * 8 + h] * bv;
    }
}

// ---------------------------------------------------------------------------
extern "C" void kernel_launch(void* const* d_in, const int* in_sizes, int n_in,
                              void* d_out, int out_size)
{
    const float* query_embed = (const float*)d_in[0];
    const float* ctrl        = (const float*)d_in[1];
    const float* bev         = (const float*)d_in[2];
    /* d_in[3] spatial_shapes unused */
    const float* pc_range    = (const float*)d_in[4];
    const float* W_q   = (const float*)d_in[5];
    const float* b_q   = (const float*)d_in[6];
    const float* W_val = (const float*)d_in[7];
    const float* b_val = (const float*)d_in[8];
    const float* W_off = (const float*)d_in[9];
    const float* b_off = (const float*)d_in[10];
    const float* W_attn = (const float*)d_in[11];
    const float* b_attn = (const float*)d_in[12];
    const float* W_do  = (const float*)d_in[13];
    const float* b_do  = (const float*)d_in[14];
    const float* W_out = (const float*)d_in[15];
    const float* b_out = (const float*)d_in[16];
    float* out = (float*)d_out;

    float *pqoa, *pWaug, *pbaug, *pWfold, *pbfold, *pg, *pws, *ps;
    __half *pbTh;
    cudaGetSymbolAddress((void**)&pqoa,  g_qoa);
    cudaGetSymbolAddress((void**)&pWaug, g_Waug);
    cudaGetSymbolAddress((void**)&pbaug, g_baug);
    cudaGetSymbolAddress((void**)&pWfold, g_Wfold);
    cudaGetSymbolAddress((void**)&pbfold, g_bfold);
    cudaGetSymbolAddress((void**)&pg,    g_gath);
    cudaGetSymbolAddress((void**)&pws,   g_wsum);
    cudaGetSymbolAddress((void**)&pbTh,  g_bevTh);
    cudaGetSymbolAddress((void**)&ps,    g_samp);

    static cudaStream_t s1 = nullptr, s2 = nullptr;
    static cudaEvent_t evFork = nullptr, evT = nullptr, evS2 = nullptr;
    if (s1 == nullptr) {
        cudaStreamCreateWithFlags(&s1, cudaStreamNonBlocking);
        cudaStreamCreateWithFlags(&s2, cudaStreamNonBlocking);
        cudaEventCreateWithFlags(&evFork, cudaEventDisableTiming);
        cudaEventCreateWithFlags(&evT,    cudaEventDisableTiming);
        cudaEventCreateWithFlags(&evS2,   cudaEventDisableTiming);
    }

    cudaEventRecord(evFork, 0);
    cudaStreamWaitEvent(s1, evFork, 0);
    cudaStreamWaitEvent(s2, evFork, 0);

    // s1: monolithic DRAM-bound transpose (fp16 output)
    transpose_h<<<dim3(NHW / 64, DIM / 32, NB), 256, 0, s1>>>(bev, pbTh);
    cudaEventRecord(evT, s1);

    // s2: contention-free weight/bias folds for output GEMM
    prep_bfold<<<1, 256, 0, s2>>>(b_q, b_do, b_out, W_out, pbfold);
    fold8<<<64, 256, 0, s2>>>(W_do, W_q, W_out, pWfold);
    cudaEventRecord(evS2, s2);

    // main: offsets/logits path (fully parallel prep + 128-block GEMM)
    prep_w<<<257, 128>>>(W_q, W_off, W_attn, b_q, b_off, b_attn, pWaug, pbaug);
    gemm_qoa<<<dim3(NAUG / 64, NROWS / 64), 256>>>(query_embed, pWaug, pbaug, pqoa);

    cudaStreamWaitEvent(0, evT, 0);

    // gather (dedup, fp16, 8 blocks/SM) + per-head projection
    gather_kernel<<<NROWS, 256>>>(ctrl, pc_range, pbTh, pqoa, pg, pws);
    proj_kernel<<<dim3(NROWS / 128, NHEADS), 256>>>(pg, pws, W_val, b_val, ps);

    cudaStreamWaitEvent(0, evS2, 0);

    // out = samp@(W_do W_out) + qe@(W_q W_out) + b_fold
    gemm_dual64<<<dim3(DIM / 64, NROWS / 64), 256>>>(
        ps, query_embed, pWfold, pbfold, out);
}

// round 11
// speedup vs baseline: 1.3389x; 1.0491x over previous
#include <cuda_runtime.h>
#include <cuda_fp16.h>
#include <math.h>

#define NB     4
#define NQ     1024
#define DIM    256
#define NHEADS 8
#define GH     200
#define GW     200
#define NHW    (GH*GW)       // 40000
#define NROWS  (NB*NQ)       // 4096
#define NAUG   128           // 64 off | 32 attn logits | 32 pad

// Scratch (__device__ globals: allocation-free per harness rules)
__device__ float  g_qoa  [NROWS * NAUG];
__device__ float  g_Waug [DIM * NAUG];
__device__ float  g_baug [NAUG];
__device__ float  g_Wfold[512 * DIM];                     // [W_do@W_out ; W_q@W_out]
__device__ float  g_bfold[DIM];
__device__ float  g_gath [(size_t)NROWS * NHEADS * DIM];  // 32 MB
__device__ float  g_wsum [NROWS * NHEADS];
__device__ __half g_bevTh[(size_t)NB * NHW * DIM];        // 82 MB fp16 [B, HW, C]
__device__ float  g_samp [NROWS * DIM];

// ---------------------------------------------------------------------------
// prep_w: one block per k-row (257 blocks; row 256 = bias), split-K in halves.
// ---------------------------------------------------------------------------
__global__ __launch_bounds__(256)
void prep_w(const float* __restrict__ W_q, const float* __restrict__ W_off,
            const float* __restrict__ W_attn,
            const float* __restrict__ b_q, const float* __restrict__ b_off,
            const float* __restrict__ b_attn,
            float* __restrict__ W_aug, float* __restrict__ b_aug)
{
    const int k = blockIdx.x;     // 0..256
    const int t = threadIdx.x;    // 0..255
    __shared__ float a[256];
    __shared__ float partial[128];
    const float* src = (k < 256) ? (W_q + (size_t)k * 256) : b_q;
    a[t] = src[t];
    __syncthreads();

    const int half = t >> 7;      // 0 or 1
    const int j = t & 127;
    const int i0 = half * 128;
    float v = 0.f;
    if (j < 64) {
#pragma unroll 8
        for (int i = 0; i < 128; i++) v = fmaf(a[i0 + i], W_off[(i0 + i) * 64 + j], v);
    } else if (j < 96) {
        const int jj = j - 64;
#pragma unroll 8
        for (int i = 0; i < 128; i++) v = fmaf(a[i0 + i], W_attn[(i0 + i) * 32 + jj], v);
    }
    if (half == 1) partial[j] = v;
    __syncthreads();
    if (half == 0) {
        v += partial[j];
        if (k == 256) {
            if (j < 64) v += b_off[j];
            else if (j < 96) v += b_attn[j - 64];
            b_aug[j] = v;
        } else {
            W_aug[(size_t)k * 128 + j] = v;
        }
    }
}

// b_fold = (b_do + b_q) @ W_out + b_out
__global__ void prep_bfold(const float* __restrict__ b_q, const float* __restrict__ b_do,
                           const float* __restrict__ b_out, const float* __restrict__ W_out,
                           float* __restrict__ bf)
{
    const int n = threadIdx.x;   // 256
    __shared__ float bs[256];
    bs[n] = b_do[n] + b_q[n];
    __syncthreads();
    float s = b_out[n];
#pragma unroll 8
    for (int k = 0; k < 256; k++) s = fmaf(bs[k], W_out[k * 256 + n], s);
    bf[n] = s;
}

// ---------------------------------------------------------------------------
// fold8: Wfold[0:256]=W_do@W_out ; [256:512]=W_q@W_out. 64 blocks, 8 rows each.
// ---------------------------------------------------------------------------
__global__ __launch_bounds__(256)
void fold8(const float* __restrict__ W_do, const float* __restrict__ W_q,
           const float* __restrict__ W_out, float* __restrict__ Wfold)
{
    const int t = threadIdx.x;
    const int r0 = blockIdx.x * 8;
    __shared__ float a[8][256];
    for (int i = t; i < 2048; i += 256) {
        const int r = r0 + (i >> 8);
        const float* src = (r < 256) ? (W_do + (size_t)r * 256)
                                     : (W_q + (size_t)(r - 256) * 256);
        a[i >> 8][i & 255] = src[i & 255];
    }
    __syncthreads();

    float acc[8];
#pragma unroll
    for (int r = 0; r < 8; r++) acc[r] = 0.f;
#pragma unroll 4
    for (int k = 0; k < 256; k++) {
        const float w = W_out[(size_t)k * 256 + t];
#pragma unroll
        for (int r = 0; r < 8; r++) acc[r] = fmaf(a[r][k], w, acc[r]);
    }
#pragma unroll
    for (int r = 0; r < 8; r++)
        Wfold[(size_t)(r0 + r) * 256 + t] = acc[r];
}

// ---------------------------------------------------------------------------
// qoa GEMM: C[4096 x 128] = A[4096 x 256] @ W[256 x 128] + bias.
// BM=64, BN=64, BK=16, 256 threads, 4x4 microtile. 128 blocks.
// ---------------------------------------------------------------------------
__global__ __launch_bounds__(256)
void gemm_qoa(const float* __restrict__ A, const float* __restrict__ W,
              const float* __restrict__ bias, float* __restrict__ C)
{
    __shared__ float As[16][68];
    __shared__ __align__(16) float Bs[16][64];

    const int tid = threadIdx.x;
    const int tx = tid & 15, ty = tid >> 4;
    const int n0 = blockIdx.x * 64;
    const int m0 = blockIdx.y * 64;

    float acc[4][4];
#pragma unroll
    for (int i = 0; i < 4; i++)
#pragma unroll
        for (int j = 0; j < 4; j++) acc[i][j] = 0.f;

    for (int k0 = 0; k0 < 256; k0 += 16) {
        {
            const int m = tid >> 2;
            const int kq = (tid & 3) * 4;
            float4 v = *(const float4*)(A + (size_t)(m0 + m) * 256 + k0 + kq);
            As[kq + 0][m] = v.x; As[kq + 1][m] = v.y;
            As[kq + 2][m] = v.z; As[kq + 3][m] = v.w;
        }
        {
            const int kr = tid >> 4;
            const int nq = (tid & 15) * 4;
            *(float4*)&Bs[kr][nq] = *(const float4*)(W + (size_t)(k0 + kr) * 128 + n0 + nq);
        }
        __syncthreads();

#pragma unroll
        for (int k = 0; k < 16; k++) {
            float a[4], b[4];
#pragma unroll
            for (int i = 0; i < 4; i++) a[i] = As[k][ty * 4 + i];
#pragma unroll
            for (int j = 0; j < 4; j++) b[j] = Bs[k][tx * 4 + j];
#pragma unroll
            for (int i = 0; i < 4; i++)
#pragma unroll
                for (int j = 0; j < 4; j++)
                    acc[i][j] = fmaf(a[i], b[j], acc[i][j]);
        }
        __syncthreads();
    }

#pragma unroll
    for (int i = 0; i < 4; i++) {
        const int m = m0 + ty * 4 + i;
#pragma unroll
        for (int j = 0; j < 4; j++) {
            const int n = n0 + tx * 4 + j;
            C[(size_t)m * 128 + n] = acc[i][j] + bias[n];
        }
    }
}

// ---------------------------------------------------------------------------
// Dual-A GEMM (K=512): C = [A1 | A2] @ W512 + bias. BM=64, BN=64, 256 blocks.
// ---------------------------------------------------------------------------
__global__ __launch_bounds__(256)
void gemm_dual64(const float* __restrict__ A1, const float* __restrict__ A2,
                 const float* __restrict__ W, const float* __restrict__ bias,
                 float* __restrict__ C)
{
    __shared__ float As[16][68];
    __shared__ __align__(16) float Bs[16][64];

    const int tid = threadIdx.x;
    const int tx = tid & 15, ty = tid >> 4;
    const int n0 = blockIdx.x * 64;
    const int m0 = blockIdx.y * 64;

    float acc[4][4];
#pragma unroll
    for (int i = 0; i < 4; i++)
#pragma unroll
        for (int j = 0; j < 4; j++) acc[i][j] = 0.f;

    for (int k0 = 0; k0 < 512; k0 += 16) {
        const float* A = (k0 < 256) ? A1 : A2;
        const int kk = k0 & 255;
        {
            const int m = tid >> 2;
            const int kq = (tid & 3) * 4;
            float4 v = *(const float4*)(A + (size_t)(m0 + m) * 256 + kk + kq);
            As[kq + 0][m] = v.x; As[kq + 1][m] = v.y;
            As[kq + 2][m] = v.z; As[kq + 3][m] = v.w;
        }
        {
            const int kr = tid >> 4;
            const int nq = (tid & 15) * 4;
            *(float4*)&Bs[kr][nq] = *(const float4*)(W + (size_t)(k0 + kr) * 256 + n0 + nq);
        }
        __syncthreads();

#pragma unroll
        for (int k = 0; k < 16; k++) {
            float a[4], b[4];
#pragma unroll
            for (int i = 0; i < 4; i++) a[i] = As[k][ty * 4 + i];
#pragma unroll
            for (int j = 0; j < 4; j++) b[j] = Bs[k][tx * 4 + j];
#pragma unroll
            for (int i = 0; i < 4; i++)
#pragma unroll
                for (int j = 0; j < 4; j++)
                    acc[i][j] = fmaf(a[i], b[j], acc[i][j]);
        }
        __syncthreads();
    }

#pragma unroll
    for (int i = 0; i < 4; i++) {
        const int m = m0 + ty * 4 + i;
#pragma unroll
        for (int j = 0; j < 4; j++) {
            const int n = n0 + tx * 4 + j;
            C[(size_t)m * 256 + n] = acc[i][j] + bias[n];
        }
    }
}

// ---------------------------------------------------------------------------
// Monolithic transpose bev [B, C=256, HW] -> bevTh [B, HW, C] in fp16.
// ---------------------------------------------------------------------------
__global__ __launch_bounds__(256)
void transpose_h(const float* __restrict__ src, __half* __restrict__ dst)
{
    __shared__ float tile[32 * 65];
    const int b  = blockIdx.z;
    const int p0 = blockIdx.x * 64;
    const int c0 = blockIdx.y * 32;
    const int tid = threadIdx.x;

#pragma unroll
    for (int l = 0; l < 2; l++) {
        const int c = l * 16 + (tid >> 4);
        const int p = (tid & 15) * 4;
        float4 v = *(const float4*)(src + ((size_t)(b * 256 + c0 + c)) * NHW + p0 + p);
        tile[c * 65 + p + 0] = v.x;
        tile[c * 65 + p + 1] = v.y;
        tile[c * 65 + p + 2] = v.z;
        tile[c * 65 + p + 3] = v.w;
    }
    __syncthreads();

#pragma unroll
    for (int l = 0; l < 2; l++) {
        const int p  = l * 32 + (tid >> 3);
        const int cq = (tid & 7) * 4;
        const __half2 h01 = __floats2half2_rn(tile[(cq + 0) * 65 + p], tile[(cq + 1) * 65 + p]);
        const __half2 h23 = __floats2half2_rn(tile[(cq + 2) * 65 + p], tile[(cq + 3) * 65 + p]);
        uint2 u;
        u.x = *reinterpret_cast<const unsigned*>(&h01);
        u.y = *reinterpret_cast<const unsigned*>(&h23);
        *(uint2*)(dst + ((size_t)b * NHW + p0 + p) * 256 + c0 + cq) = u;
    }
}

// ---------------------------------------------------------------------------
// Gather with pixel dedup (fp16), 4-deep software-pipelined pixel loop.
// ---------------------------------------------------------------------------
__global__ __launch_bounds__(256)
void gather_kernel(const float* __restrict__ ctrl, const float* __restrict__ pcr,
                   const __half* __restrict__ bevT, const float* __restrict__ qoa,
                   float* __restrict__ g, float* __restrict__ wsum)
{
    const int row = blockIdx.x;
    const int b = row >> 10;
    const int t = threadIdx.x;

    __shared__ int    s_idx[128];
    __shared__ float  s_w[128];
    __shared__ float  ws[32];
    __shared__ int    hidx[256];
    __shared__ float  hw[256][8];
    __shared__ int    slots[128];
    __shared__ int    cnt;
    __shared__ float4 red[2 * 8 * 64];   // 16 KB two-round reduction buffer

    hidx[t] = -1;
    {
        float* hwf = &hw[0][0];
#pragma unroll
        for (int i = 0; i < 8; i++) hwf[t + 256 * i] = 0.f;
    }
    if (t == 0) cnt = 0;

    if (t < 32) {
        const float lox = pcr[0], loy = pcr[1];
        const float spx = pcr[3] - pcr[0], spy = pcr[4] - pcr[1];
        const float* cp = ctrl + (size_t)row * 8;
        const float c0x = cp[0], c0y = cp[1], c1x = cp[2], c1y = cp[3];
        const float c2x = cp[4], c2y = cp[5], c3x = cp[6], c3y = cp[7];
        float sx = 0.f, sy = 0.f;
#pragma unroll
        for (int k = 0; k < 10; k++) {
            const float tt = (float)k / 9.0f;
            const float u = 1.0f - tt;
            const float w0 = u*u*u, w1 = 3.f*u*u*tt, w2 = 3.f*u*tt*tt, w3 = tt*tt*tt;
            const float dx = w0*c0x + w1*c1x + w2*c2x + w3*c3x;
            const float dy = w0*c0y + w1*c1y + w2*c2y + w3*c3y;
            sx += fminf(fmaxf((dx - lox) / spx, 0.01f), 0.99f);
            sy += fminf(fmaxf((dy - loy) / spy, 0.01f), 0.99f);
        }
        const float rcx = sx * 0.1f, rcy = sy * 0.1f;

        const int h = t >> 2, p = t & 3;
        const float* lg = qoa + (size_t)row * NAUG + 64 + h * 4;
        const float l0 = lg[0], l1 = lg[1], l2 = lg[2], l3 = lg[3];
        const float m = fmaxf(fmaxf(l0, l1), fmaxf(l2, l3));
        const float e0 = expf(l0 - m), e1 = expf(l1 - m), e2 = expf(l2 - m), e3 = expf(l3 - m);
        const float lp = (p == 0) ? l0 : (p == 1) ? l1 : (p == 2) ? l2 : l3;
        const float aw = expf(lp - m) / (e0 + e1 + e2 + e3);

        const float ox = qoa[(size_t)row * NAUG + h * 8 + p * 2 + 0];
        const float oy = qoa[(size_t)row * NAUG + h * 8 + p * 2 + 1];
        const float x = (rcx + ox / (float)GW) * (float)GW - 0.5f;
        const float y = (rcy + oy / (float)GH) * (float)GH - 0.5f;
        const float fx = floorf(x), fy = floorf(y);
        const int x0 = (int)fx, y0 = (int)fy;
        const int x1 = x0 + 1,  y1 = y0 + 1;
        const float wx = x - fx, wy = y - fy;
        const bool vx0 = (x0 >= 0) & (x0 < GW), vx1 = (x1 >= 0) & (x1 < GW);
        const bool vy0 = (y0 >= 0) & (y0 < GH), vy1 = (y1 >= 0) & (y1 < GH);
        const int cx0 = min(max(x0, 0), GW - 1), cx1 = min(max(x1, 0), GW - 1);
        const int cy0 = min(max(y0, 0), GH - 1), cy1 = min(max(y1, 0), GH - 1);
        const float w00 = (vy0 & vx0) ? (1.f - wx) * (1.f - wy) * aw : 0.f;
        const float w01 = (vy0 & vx1) ? wx * (1.f - wy) * aw : 0.f;
        const float w10 = (vy1 & vx0) ? (1.f - wx) * wy * aw : 0.f;
        const float w11 = (vy1 & vx1) ? wx * wy * aw : 0.f;
        s_idx[t*4+0] = cy0 * GW + cx0;  s_w[t*4+0] = w00;
        s_idx[t*4+1] = cy0 * GW + cx1;  s_w[t*4+1] = w01;
        s_idx[t*4+2] = cy1 * GW + cx0;  s_w[t*4+2] = w10;
        s_idx[t*4+3] = cy1 * GW + cx1;  s_w[t*4+3] = w11;
        ws[t] = w00 + w01 + w10 + w11;
    }
    __syncthreads();

    if (t < 128) {
        const int idx = s_idx[t];
        const float w = s_w[t];
        const int h = t >> 4;
        unsigned s = ((unsigned)idx * 2654435761u) >> 24;
        while (true) {
            int prev = atomicCAS(&hidx[s], -1, idx);
            if (prev == -1 || prev == idx) { atomicAdd(&hw[s][h], w); break; }
            s = (s + 1) & 255;
        }
    }
    __syncthreads();

    if (hidx[t] >= 0) {
        const int p = atomicAdd(&cnt, 1);
        slots[p] = t;
    }
    __syncthreads();

    const int cq = t & 63;
    const int stripe = t >> 6;
    float4 acc8[8];
#pragma unroll
    for (int h = 0; h < 8; h++) acc8[h] = make_float4(0.f, 0.f, 0.f, 0.f);

    const int n = cnt;
    const __half* basep = bevT + ((size_t)b * NHW) * 256 + cq * 4;

    int i = stripe;
    // 4-deep pipelined main loop
    for (; i + 12 < n; i += 16) {
        const int sl0 = slots[i], sl1 = slots[i + 4], sl2 = slots[i + 8], sl3 = slots[i + 12];
        const uint2 r0 = *(const uint2*)(basep + (size_t)hidx[sl0] * 256);
        const uint2 r1 = *(const uint2*)(basep + (size_t)hidx[sl1] * 256);
        const uint2 r2 = *(const uint2*)(basep + (size_t)hidx[sl2] * 256);
        const uint2 r3 = *(const uint2*)(basep + (size_t)hidx[sl3] * 256);
        const float2 a01 = __half22float2(*reinterpret_cast<const __half2*>(&r0.x));
        const float2 a23 = __half22float2(*reinterpret_cast<const __half2*>(&r0.y));
        const float2 b01 = __half22float2(*reinterpret_cast<const __half2*>(&r1.x));
        const float2 b23 = __half22float2(*reinterpret_cast<const __half2*>(&r1.y));
        const float2 c01 = __half22float2(*reinterpret_cast<const __half2*>(&r2.x));
        const float2 c23 = __half22float2(*reinterpret_cast<const __half2*>(&r2.y));
        const float2 d01 = __half22float2(*reinterpret_cast<const __half2*>(&r3.x));
        const float2 d23 = __half22float2(*reinterpret_cast<const __half2*>(&r3.y));
#pragma unroll
        for (int h = 0; h < 8; h++) {
            const float w0 = hw[sl0][h], w1 = hw[sl1][h], w2 = hw[sl2][h], w3 = hw[sl3][h];
            acc8[h].x = fmaf(w3, d01.x, fmaf(w2, c01.x, fmaf(w1, b01.x, fmaf(w0, a01.x, acc8[h].x))));
            acc8[h].y = fmaf(w3, d01.y, fmaf(w2, c01.y, fmaf(w1, b01.y, fmaf(w0, a01.y, acc8[h].y))));
            acc8[h].z = fmaf(w3, d23.x, fmaf(w2, c23.x, fmaf(w1, b23.x, fmaf(w0, a23.x, acc8[h].z))));
            acc8[h].w = fmaf(w3, d23.y, fmaf(w2, c23.y, fmaf(w1, b23.y, fmaf(w0, a23.y, acc8[h].w))));
        }
    }
    for (; i < n; i += 4) {
        const int slot = slots[i];
        const uint2 raw = *(const uint2*)(basep + (size_t)hidx[slot] * 256);
        const float2 f01 = __half22float2(*reinterpret_cast<const __half2*>(&raw.x));
        const float2 f23 = __half22float2(*reinterpret_cast<const __half2*>(&raw.y));
#pragma unroll
        for (int h = 0; h < 8; h++) {
            const float w = hw[slot][h];
            acc8[h].x = fmaf(w, f01.x, acc8[h].x);
            acc8[h].y = fmaf(w, f01.y, acc8[h].y);
            acc8[h].z = fmaf(w, f23.x, acc8[h].z);
            acc8[h].w = fmaf(w, f23.y, acc8[h].w);
        }
    }

    // Round 1: stripes 2,3 -> smem; 0,1 accumulate. Round 2: 1 -> smem; 0 writes.
    if (stripe >= 2) {
#pragma unroll
        for (int h = 0; h < 8; h++)
            red[((stripe - 2) * 8 + h) * 64 + cq] = acc8[h];
    }
    __syncthreads();
    if (stripe < 2) {
#pragma unroll
        for (int h = 0; h < 8; h++) {
            const float4 v = red[(stripe * 8 + h) * 64 + cq];
            acc8[h].x += v.x; acc8[h].y += v.y; acc8[h].z += v.z; acc8[h].w += v.w;
        }
    }
    __syncthreads();
    if (stripe == 1) {
#pragma unroll
        for (int h = 0; h < 8; h++)
            red[h * 64 + cq] = acc8[h];
    }
    __syncthreads();
    if (stripe == 0) {
#pragma unroll
        for (int h = 0; h < 8; h++) {
            const float4 v = red[h * 64 + cq];
            acc8[h].x += v.x; acc8[h].y += v.y; acc8[h].z += v.z; acc8[h].w += v.w;
            *(float4*)(g + ((size_t)row * 8 + h) * 256 + cq * 4) = acc8[h];
        }
    }

    if (t < 8)
        wsum[(size_t)row * 8 + t] = ws[t*4] + ws[t*4+1] + ws[t*4+2] + ws[t*4+3];
}

// ---------------------------------------------------------------------------
// Block-diagonal projection.
// ---------------------------------------------------------------------------
__global__ __launch_bounds__(256)
void proj_kernel(const float* __restrict__ g, const float* __restrict__ wsum,
                 const float* __restrict__ W_val, const float* __restrict__ b_val,
                 float* __restrict__ samp)
{
    const int h  = blockIdx.y;
    const int r0 = blockIdx.x * 128;
    const int t  = threadIdx.x;
    const int d = t & 31, rg = t >> 5;

    __shared__ float Ws[256 * 32];
    __shared__ float As[128 * 36];

#pragma unroll
    for (int i = 0; i < 32; i++) {
        const int k = i * 8 + (t >> 5);
        Ws[k * 32 + d] = W_val[(size_t)k * 256 + h * 32 + d];
    }
    const float bv = b_val[h * 32 + d];

    float acc[16];
#pragma unroll
    for (int r = 0; r < 16; r++) acc[r] = 0.f;

    for (int kt = 0; kt < 8; kt++) {
        __syncthreads();
        {
            const int i = t >> 1, half = t & 1;
            const float* src = g + ((size_t)(r0 + i) * 8 + h) * 256 + kt * 32 + half * 16;
            float* dst = &As[i * 36 + half * 16];
#pragma unroll
            for (int q = 0; q < 4; q++)
                *(float4*)(dst + q * 4) = *(const float4*)(src + q * 4);
        }
        __syncthreads();

#pragma unroll
        for (int k = 0; k < 32; k++) {
            const float wv = Ws[(kt * 32 + k) * 32 + d];
#pragma unroll
            for (int r = 0; r < 16; r++)
                acc[r] = fmaf(As[(rg * 16 + r) * 36 + k], wv, acc[r]);
        }
    }

#pragma unroll
    for (int r = 0; r < 16; r++) {
        const int row = r0 + rg * 16 + r;
        samp[(size_t)row * 256 + h * 32 + d] = acc[r] + wsum[(size_t)row * 8 + h] * bv;
    }
}

// ---------------------------------------------------------------------------
extern "C" void kernel_launch(void* const* d_in, const int* in_sizes, int n_in,
                              void* d_out, int out_size)
{
    const float* query_embed = (const float*)d_in[0];
    const float* ctrl        = (const float*)d_in[1];
    const float* bev         = (const float*)d_in[2];
    /* d_in[3] spatial_shapes unused */
    const float* pc_range    = (const float*)d_in[4];
    const float* W_q   = (const float*)d_in[5];
    const float* b_q   = (const float*)d_in[6];
    const float* W_val = (const float*)d_in[7];
    const float* b_val = (const float*)d_in[8];
    const float* W_off = (const float*)d_in[9];
    const float* b_off = (const float*)d_in[10];
    const float* W_attn = (const float*)d_in[11];
    const float* b_attn = (const float*)d_in[12];
    const float* W_do  = (const float*)d_in[13];
    const float* b_do  = (const float*)d_in[14];
    const float* W_out = (const float*)d_in[15];
    const float* b_out = (const float*)d_in[16];
    float* out = (float*)d_out;

    float *pqoa, *pWaug, *pbaug, *pWfold, *pbfold, *pg, *pws, *ps;
    __half *pbTh;
    cudaGetSymbolAddress((void**)&pqoa,  g_qoa);
    cudaGetSymbolAddress((void**)&pWaug, g_Waug);
    cudaGetSymbolAddress((void**)&pbaug, g_baug);
    cudaGetSymbolAddress((void**)&pWfold, g_Wfold);
    cudaGetSymbolAddress((void**)&pbfold, g_bfold);
    cudaGetSymbolAddress((void**)&pg,    g_gath);
    cudaGetSymbolAddress((void**)&pws,   g_wsum);
    cudaGetSymbolAddress((void**)&pbTh,  g_bevTh);
    cudaGetSymbolAddress((void**)&ps,    g_samp);

    static cudaStream_t s1 = nullptr, s2 = nullptr;
    static cudaEvent_t evFork = nullptr, evT = nullptr, evS2 = nullptr;
    if (s1 == nullptr) {
        cudaStreamCreateWithFlags(&s1, cudaStreamNonBlocking);
        cudaStreamCreateWithFlags(&s2, cudaStreamNonBlocking);
        cudaEventCreateWithFlags(&evFork, cudaEventDisableTiming);
        cudaEventCreateWithFlags(&evT,    cudaEventDisableTiming);
        cudaEventCreateWithFlags(&evS2,   cudaEventDisableTiming);
    }

    cudaEventRecord(evFork, 0);
    cudaStreamWaitEvent(s1, evFork, 0);
    cudaStreamWaitEvent(s2, evFork, 0);

    // s1: monolithic DRAM-bound transpose (fp16 output)
    transpose_h<<<dim3(NHW / 64, DIM / 32, NB), 256, 0, s1>>>(bev, pbTh);
    cudaEventRecord(evT, s1);

    // s2: contention-free weight/bias folds for output GEMM
    prep_bfold<<<1, 256, 0, s2>>>(b_q, b_do, b_out, W_out, pbfold);
    fold8<<<64, 256, 0, s2>>>(W_do, W_q, W_out, pWfold);
    cudaEventRecord(evS2, s2);

    // main: offsets/logits path (split-K prep + 128-block GEMM)
    prep_w<<<257, 256>>>(W_q, W_off, W_attn, b_q, b_off, b_attn, pWaug, pbaug);
    gemm_qoa<<<dim3(NAUG / 64, NROWS / 64), 256>>>(query_embed, pWaug, pbaug, pqoa);

    cudaStreamWaitEvent(0, evT, 0);

    // gather (dedup, fp16, 4-deep pipelined) + per-head projection
    gather_kernel<<<NROWS, 256>>>(ctrl, pc_range, pbTh, pqoa, pg, pws);
    proj_kernel<<<dim3(NROWS / 128, NHEADS), 256>>>(pg, pws, W_val, b_val, ps);

    cudaStreamWaitEvent(0, evS2, 0);

    // out = samp@(W_do W_out) + qe@(W_q W_out) + b_fold
    gemm_dual64<<<dim3(DIM / 64, NROWS / 64), 256>>>(
        ps, query_embed, pWfold, pbfold, out);
}

// round 12
// speedup vs baseline: 1.3509x; 1.0089x over previous
#include <cuda_runtime.h>
#include <cuda_fp16.h>
#include <math.h>

#define NB     4
#define NQ     1024
#define DIM    256
#define NHEADS 8
#define GH     200
#define GW     200
#define NHW    (GH*GW)       // 40000
#define NROWS  (NB*NQ)       // 4096
#define NAUG   128           // 64 off | 32 attn logits | 32 pad

// Scratch (__device__ globals: allocation-free per harness rules)
__device__ float  g_qoa  [NROWS * NAUG];
__device__ float  g_Waug [DIM * NAUG];
__device__ float  g_baug [NAUG];
__device__ float  g_Wfold[512 * DIM];                     // [W_do@W_out ; W_q@W_out]
__device__ float  g_bfold[DIM];
__device__ float  g_gath [(size_t)NROWS * NHEADS * DIM];  // 32 MB
__device__ float  g_wsum [NROWS * NHEADS];
__device__ __half g_bevTh[(size_t)NB * NHW * DIM];        // 82 MB fp16 [B, HW, C]
__device__ float  g_samp [NROWS * DIM];

// ---------------------------------------------------------------------------
// prep_w: one block per k-row (257 blocks; row 256 = bias), split-K in halves.
// ---------------------------------------------------------------------------
__global__ __launch_bounds__(256)
void prep_w(const float* __restrict__ W_q, const float* __restrict__ W_off,
            const float* __restrict__ W_attn,
            const float* __restrict__ b_q, const float* __restrict__ b_off,
            const float* __restrict__ b_attn,
            float* __restrict__ W_aug, float* __restrict__ b_aug)
{
    const int k = blockIdx.x;     // 0..256
    const int t = threadIdx.x;    // 0..255
    __shared__ float a[256];
    __shared__ float partial[128];
    const float* src = (k < 256) ? (W_q + (size_t)k * 256) : b_q;
    a[t] = src[t];
    __syncthreads();

    const int half = t >> 7;      // 0 or 1
    const int j = t & 127;
    const int i0 = half * 128;
    float v = 0.f;
    if (j < 64) {
#pragma unroll 8
        for (int i = 0; i < 128; i++) v = fmaf(a[i0 + i], W_off[(i0 + i) * 64 + j], v);
    } else if (j < 96) {
        const int jj = j - 64;
#pragma unroll 8
        for (int i = 0; i < 128; i++) v = fmaf(a[i0 + i], W_attn[(i0 + i) * 32 + jj], v);
    }
    if (half == 1) partial[j] = v;
    __syncthreads();
    if (half == 0) {
        v += partial[j];
        if (k == 256) {
            if (j < 64) v += b_off[j];
            else if (j < 96) v += b_attn[j - 64];
            b_aug[j] = v;
        } else {
            W_aug[(size_t)k * 128 + j] = v;
        }
    }
}

// b_fold = (b_do + b_q) @ W_out + b_out
__global__ void prep_bfold(const float* __restrict__ b_q, const float* __restrict__ b_do,
                           const float* __restrict__ b_out, const float* __restrict__ W_out,
                           float* __restrict__ bf)
{
    const int n = threadIdx.x;   // 256
    __shared__ float bs[256];
    bs[n] = b_do[n] + b_q[n];
    __syncthreads();
    float s = b_out[n];
#pragma unroll 8
    for (int k = 0; k < 256; k++) s = fmaf(bs[k], W_out[k * 256 + n], s);
    bf[n] = s;
}

// ---------------------------------------------------------------------------
// fold8: Wfold[0:256]=W_do@W_out ; [256:512]=W_q@W_out. 64 blocks, 8 rows each.
// ---------------------------------------------------------------------------
__global__ __launch_bounds__(256)
void fold8(const float* __restrict__ W_do, const float* __restrict__ W_q,
           const float* __restrict__ W_out, float* __restrict__ Wfold)
{
    const int t = threadIdx.x;
    const int r0 = blockIdx.x * 8;
    __shared__ float a[8][256];
    for (int i = t; i < 2048; i += 256) {
        const int r = r0 + (i >> 8);
        const float* src = (r < 256) ? (W_do + (size_t)r * 256)
                                     : (W_q + (size_t)(r - 256) * 256);
        a[i >> 8][i & 255] = src[i & 255];
    }
    __syncthreads();

    float acc[8];
#pragma unroll
    for (int r = 0; r < 8; r++) acc[r] = 0.f;
#pragma unroll 4
    for (int k = 0; k < 256; k++) {
        const float w = W_out[(size_t)k * 256 + t];
#pragma unroll
        for (int r = 0; r < 8; r++) acc[r] = fmaf(a[r][k], w, acc[r]);
    }
#pragma unroll
    for (int r = 0; r < 8; r++)
        Wfold[(size_t)(r0 + r) * 256 + t] = acc[r];
}

// ---------------------------------------------------------------------------
// qoa GEMM: C[4096 x 128] = A[4096 x 256] @ W[256 x 128] + bias.
// BM=64, BN=64, BK=16, 256 threads, 4x4 microtile. 128 blocks.
// ---------------------------------------------------------------------------
__global__ __launch_bounds__(256)
void gemm_qoa(const float* __restrict__ A, const float* __restrict__ W,
              const float* __restrict__ bias, float* __restrict__ C)
{
    __shared__ float As[16][68];
    __shared__ __align__(16) float Bs[16][64];

    const int tid = threadIdx.x;
    const int tx = tid & 15, ty = tid >> 4;
    const int n0 = blockIdx.x * 64;
    const int m0 = blockIdx.y * 64;

    float acc[4][4];
#pragma unroll
    for (int i = 0; i < 4; i++)
#pragma unroll
        for (int j = 0; j < 4; j++) acc[i][j] = 0.f;

    for (int k0 = 0; k0 < 256; k0 += 16) {
        {
            const int m = tid >> 2;
            const int kq = (tid & 3) * 4;
            float4 v = *(const float4*)(A + (size_t)(m0 + m) * 256 + k0 + kq);
            As[kq + 0][m] = v.x; As[kq + 1][m] = v.y;
            As[kq + 2][m] = v.z; As[kq + 3][m] = v.w;
        }
        {
            const int kr = tid >> 4;
            const int nq = (tid & 15) * 4;
            *(float4*)&Bs[kr][nq] = *(const float4*)(W + (size_t)(k0 + kr) * 128 + n0 + nq);
        }
        __syncthreads();

#pragma unroll
        for (int k = 0; k < 16; k++) {
            float a[4], b[4];
#pragma unroll
            for (int i = 0; i < 4; i++) a[i] = As[k][ty * 4 + i];
#pragma unroll
            for (int j = 0; j < 4; j++) b[j] = Bs[k][tx * 4 + j];
#pragma unroll
            for (int i = 0; i < 4; i++)
#pragma unroll
                for (int j = 0; j < 4; j++)
                    acc[i][j] = fmaf(a[i], b[j], acc[i][j]);
        }
        __syncthreads();
    }

#pragma unroll
    for (int i = 0; i < 4; i++) {
        const int m = m0 + ty * 4 + i;
#pragma unroll
        for (int j = 0; j < 4; j++) {
            const int n = n0 + tx * 4 + j;
            C[(size_t)m * 128 + n] = acc[i][j] + bias[n];
        }
    }
}

// ---------------------------------------------------------------------------
// Dual-A GEMM (K=512): C = [A1 | A2] @ W512 + bias. BM=64, BN=64, 256 blocks.
// ---------------------------------------------------------------------------
__global__ __launch_bounds__(256)
void gemm_dual64(const float* __restrict__ A1, const float* __restrict__ A2,
                 const float* __restrict__ W, const float* __restrict__ bias,
                 float* __restrict__ C)
{
    __shared__ float As[16][68];
    __shared__ __align__(16) float Bs[16][64];

    const int tid = threadIdx.x;
    const int tx = tid & 15, ty = tid >> 4;
    const int n0 = blockIdx.x * 64;
    const int m0 = blockIdx.y * 64;

    float acc[4][4];
#pragma unroll
    for (int i = 0; i < 4; i++)
#pragma unroll
        for (int j = 0; j < 4; j++) acc[i][j] = 0.f;

    for (int k0 = 0; k0 < 512; k0 += 16) {
        const float* A = (k0 < 256) ? A1 : A2;
        const int kk = k0 & 255;
        {
            const int m = tid >> 2;
            const int kq = (tid & 3) * 4;
            float4 v = *(const float4*)(A + (size_t)(m0 + m) * 256 + kk + kq);
            As[kq + 0][m] = v.x; As[kq + 1][m] = v.y;
            As[kq + 2][m] = v.z; As[kq + 3][m] = v.w;
        }
        {
            const int kr = tid >> 4;
            const int nq = (tid & 15) * 4;
            *(float4*)&Bs[kr][nq] = *(const float4*)(W + (size_t)(k0 + kr) * 256 + n0 + nq);
        }
        __syncthreads();

#pragma unroll
        for (int k = 0; k < 16; k++) {
            float a[4], b[4];
#pragma unroll
            for (int i = 0; i < 4; i++) a[i] = As[k][ty * 4 + i];
#pragma unroll
            for (int j = 0; j < 4; j++) b[j] = Bs[k][tx * 4 + j];
#pragma unroll
            for (int i = 0; i < 4; i++)
#pragma unroll
                for (int j = 0; j < 4; j++)
                    acc[i][j] = fmaf(a[i], b[j], acc[i][j]);
        }
        __syncthreads();
    }

#pragma unroll
    for (int i = 0; i < 4; i++) {
        const int m = m0 + ty * 4 + i;
#pragma unroll
        for (int j = 0; j < 4; j++) {
            const int n = n0 + tx * 4 + j;
            C[(size_t)m * 256 + n] = acc[i][j] + bias[n];
        }
    }
}

// ---------------------------------------------------------------------------
// Monolithic transpose bev [B, C=256, HW] -> bevTh [B, HW, C] in fp16.
// ---------------------------------------------------------------------------
__global__ __launch_bounds__(256)
void transpose_h(const float* __restrict__ src, __half* __restrict__ dst)
{
    __shared__ float tile[32 * 65];
    const int b  = blockIdx.z;
    const int p0 = blockIdx.x * 64;
    const int c0 = blockIdx.y * 32;
    const int tid = threadIdx.x;

#pragma unroll
    for (int l = 0; l < 2; l++) {
        const int c = l * 16 + (tid >> 4);
        const int p = (tid & 15) * 4;
        float4 v = *(const float4*)(src + ((size_t)(b * 256 + c0 + c)) * NHW + p0 + p);
        tile[c * 65 + p + 0] = v.x;
        tile[c * 65 + p + 1] = v.y;
        tile[c * 65 + p + 2] = v.z;
        tile[c * 65 + p + 3] = v.w;
    }
    __syncthreads();

#pragma unroll
    for (int l = 0; l < 2; l++) {
        const int p  = l * 32 + (tid >> 3);
        const int cq = (tid & 7) * 4;
        const __half2 h01 = __floats2half2_rn(tile[(cq + 0) * 65 + p], tile[(cq + 1) * 65 + p]);
        const __half2 h23 = __floats2half2_rn(tile[(cq + 2) * 65 + p], tile[(cq + 3) * 65 + p]);
        uint2 u;
        u.x = *reinterpret_cast<const unsigned*>(&h01);
        u.y = *reinterpret_cast<const unsigned*>(&h23);
        *(uint2*)(dst + ((size_t)b * NHW + p0 + p) * 256 + c0 + cq) = u;
    }
}

// ---------------------------------------------------------------------------
// Gather with pixel dedup (fp16), 4-deep software-pipelined pixel loop.
// ---------------------------------------------------------------------------
__global__ __launch_bounds__(256)
void gather_kernel(const float* __restrict__ ctrl, const float* __restrict__ pcr,
                   const __half* __restrict__ bevT, const float* __restrict__ qoa,
                   float* __restrict__ g, float* __restrict__ wsum)
{
    const int row = blockIdx.x;
    const int b = row >> 10;
    const int t = threadIdx.x;

    __shared__ int    s_idx[128];
    __shared__ float  s_w[128];
    __shared__ float  ws[32];
    __shared__ int    hidx[256];
    __shared__ float  hw[256][8];
    __shared__ int    slots[128];
    __shared__ int    cnt;
    __shared__ float4 red[2 * 8 * 64];   // 16 KB two-round reduction buffer

    hidx[t] = -1;
    {
        float* hwf = &hw[0][0];
#pragma unroll
        for (int i = 0; i < 8; i++) hwf[t + 256 * i] = 0.f;
    }
    if (t == 0) cnt = 0;

    if (t < 32) {
        const float lox = pcr[0], loy = pcr[1];
        const float spx = pcr[3] - pcr[0], spy = pcr[4] - pcr[1];
        const float* cp = ctrl + (size_t)row * 8;
        const float c0x = cp[0], c0y = cp[1], c1x = cp[2], c1y = cp[3];
        const float c2x = cp[4], c2y = cp[5], c3x = cp[6], c3y = cp[7];
        float sx = 0.f, sy = 0.f;
#pragma unroll
        for (int k = 0; k < 10; k++) {
            const float tt = (float)k / 9.0f;
            const float u = 1.0f - tt;
            const float w0 = u*u*u, w1 = 3.f*u*u*tt, w2 = 3.f*u*tt*tt, w3 = tt*tt*tt;
            const float dx = w0*c0x + w1*c1x + w2*c2x + w3*c3x;
            const float dy = w0*c0y + w1*c1y + w2*c2y + w3*c3y;
            sx += fminf(fmaxf((dx - lox) / spx, 0.01f), 0.99f);
            sy += fminf(fmaxf((dy - loy) / spy, 0.01f), 0.99f);
        }
        const float rcx = sx * 0.1f, rcy = sy * 0.1f;

        const int h = t >> 2, p = t & 3;
        const float* lg = qoa + (size_t)row * NAUG + 64 + h * 4;
        const float l0 = lg[0], l1 = lg[1], l2 = lg[2], l3 = lg[3];
        const float m = fmaxf(fmaxf(l0, l1), fmaxf(l2, l3));
        const float e0 = expf(l0 - m), e1 = expf(l1 - m), e2 = expf(l2 - m), e3 = expf(l3 - m);
        const float lp = (p == 0) ? l0 : (p == 1) ? l1 : (p == 2) ? l2 : l3;
        const float aw = expf(lp - m) / (e0 + e1 + e2 + e3);

        const float ox = qoa[(size_t)row * NAUG + h * 8 + p * 2 + 0];
        const float oy = qoa[(size_t)row * NAUG + h * 8 + p * 2 + 1];
        const float x = (rcx + ox / (float)GW) * (float)GW - 0.5f;
        const float y = (rcy + oy / (float)GH) * (float)GH - 0.5f;
        const float fx = floorf(x), fy = floorf(y);
        const int x0 = (int)fx, y0 = (int)fy;
        const int x1 = x0 + 1,  y1 = y0 + 1;
        const float wx = x - fx, wy = y - fy;
        const bool vx0 = (x0 >= 0) & (x0 < GW), vx1 = (x1 >= 0) & (x1 < GW);
        const bool vy0 = (y0 >= 0) & (y0 < GH), vy1 = (y1 >= 0) & (y1 < GH);
        const int cx0 = min(max(x0, 0), GW - 1), cx1 = min(max(x1, 0), GW - 1);
        const int cy0 = min(max(y0, 0), GH - 1), cy1 = min(max(y1, 0), GH - 1);
        const float w00 = (vy0 & vx0) ? (1.f - wx) * (1.f - wy) * aw : 0.f;
        const float w01 = (vy0 & vx1) ? wx * (1.f - wy) * aw : 0.f;
        const float w10 = (vy1 & vx0) ? (1.f - wx) * wy * aw : 0.f;
        const float w11 = (vy1 & vx1) ? wx * wy * aw : 0.f;
        s_idx[t*4+0] = cy0 * GW + cx0;  s_w[t*4+0] = w00;
        s_idx[t*4+1] = cy0 * GW + cx1;  s_w[t*4+1] = w01;
        s_idx[t*4+2] = cy1 * GW + cx0;  s_w[t*4+2] = w10;
        s_idx[t*4+3] = cy1 * GW + cx1;  s_w[t*4+3] = w11;
        ws[t] = w00 + w01 + w10 + w11;
    }
    __syncthreads();

    if (t < 128) {
        const int idx = s_idx[t];
        const float w = s_w[t];
        const int h = t >> 4;
        unsigned s = ((unsigned)idx * 2654435761u) >> 24;
        while (true) {
            int prev = atomicCAS(&hidx[s], -1, idx);
            if (prev == -1 || prev == idx) { atomicAdd(&hw[s][h], w); break; }
            s = (s + 1) & 255;
        }
    }
    __syncthreads();

    if (hidx[t] >= 0) {
        const int p = atomicAdd(&cnt, 1);
        slots[p] = t;
    }
    __syncthreads();

    const int cq = t & 63;
    const int stripe = t >> 6;
    float4 acc8[8];
#pragma unroll
    for (int h = 0; h < 8; h++) acc8[h] = make_float4(0.f, 0.f, 0.f, 0.f);

    const int n = cnt;
    const __half* basep = bevT + ((size_t)b * NHW) * 256 + cq * 4;

    int i = stripe;
    // 4-deep pipelined main loop
    for (; i + 12 < n; i += 16) {
        const int sl0 = slots[i], sl1 = slots[i + 4], sl2 = slots[i + 8], sl3 = slots[i + 12];
        const uint2 r0 = *(const uint2*)(basep + (size_t)hidx[sl0] * 256);
        const uint2 r1 = *(const uint2*)(basep + (size_t)hidx[sl1] * 256);
        const uint2 r2 = *(const uint2*)(basep + (size_t)hidx[sl2] * 256);
        const uint2 r3 = *(const uint2*)(basep + (size_t)hidx[sl3] * 256);
        const float2 a01 = __half22float2(*reinterpret_cast<const __half2*>(&r0.x));
        const float2 a23 = __half22float2(*reinterpret_cast<const __half2*>(&r0.y));
        const float2 b01 = __half22float2(*reinterpret_cast<const __half2*>(&r1.x));
        const float2 b23 = __half22float2(*reinterpret_cast<const __half2*>(&r1.y));
        const float2 c01 = __half22float2(*reinterpret_cast<const __half2*>(&r2.x));
        const float2 c23 = __half22float2(*reinterpret_cast<const __half2*>(&r2.y));
        const float2 d01 = __half22float2(*reinterpret_cast<const __half2*>(&r3.x));
        const float2 d23 = __half22float2(*reinterpret_cast<const __half2*>(&r3.y));
#pragma unroll
        for (int h = 0; h < 8; h++) {
            const float w0 = hw[sl0][h], w1 = hw[sl1][h], w2 = hw[sl2][h], w3 = hw[sl3][h];
            acc8[h].x = fmaf(w3, d01.x, fmaf(w2, c01.x, fmaf(w1, b01.x, fmaf(w0, a01.x, acc8[h].x))));
            acc8[h].y = fmaf(w3, d01.y, fmaf(w2, c01.y, fmaf(w1, b01.y, fmaf(w0, a01.y, acc8[h].y))));
            acc8[h].z = fmaf(w3, d23.x, fmaf(w2, c23.x, fmaf(w1, b23.x, fmaf(w0, a23.x, acc8[h].z))));
            acc8[h].w = fmaf(w3, d23.y, fmaf(w2, c23.y, fmaf(w1, b23.y, fmaf(w0, a23.y, acc8[h].w))));
        }
    }
    for (; i < n; i += 4) {
        const int slot = slots[i];
        const uint2 raw = *(const uint2*)(basep + (size_t)hidx[slot] * 256);
        const float2 f01 = __half22float2(*reinterpret_cast<const __half2*>(&raw.x));
        const float2 f23 = __half22float2(*reinterpret_cast<const __half2*>(&raw.y));
#pragma unroll
        for (int h = 0; h < 8; h++) {
            const float w = hw[slot][h];
            acc8[h].x = fmaf(w, f01.x, acc8[h].x);
            acc8[h].y = fmaf(w, f01.y, acc8[h].y);
            acc8[h].z = fmaf(w, f23.x, acc8[h].z);
            acc8[h].w = fmaf(w, f23.y, acc8[h].w);
        }
    }

    // Round 1: stripes 2,3 -> smem; 0,1 accumulate. Round 2: 1 -> smem; 0 writes.
    if (stripe >= 2) {
#pragma unroll
        for (int h = 0; h < 8; h++)
            red[((stripe - 2) * 8 + h) * 64 + cq] = acc8[h];
    }
    __syncthreads();
    if (stripe < 2) {
#pragma unroll
        for (int h = 0; h < 8; h++) {
            const float4 v = red[(stripe * 8 + h) * 64 + cq];
            acc8[h].x += v.x; acc8[h].y += v.y; acc8[h].z += v.z; acc8[h].w += v.w;
        }
    }
    __syncthreads();
    if (stripe == 1) {
#pragma unroll
        for (int h = 0; h < 8; h++)
            red[h * 64 + cq] = acc8[h];
    }
    __syncthreads();
    if (stripe == 0) {
#pragma unroll
        for (int h = 0; h < 8; h++) {
            const float4 v = red[h * 64 + cq];
            acc8[h].x += v.x; acc8[h].y += v.y; acc8[h].z += v.z; acc8[h].w += v.w;
            *(float4*)(g + ((size_t)row * 8 + h) * 256 + cq * 4) = acc8[h];
        }
    }

    if (t < 8)
        wsum[(size_t)row * 8 + t] = ws[t*4] + ws[t*4+1] + ws[t*4+2] + ws[t*4+3];
}

// ---------------------------------------------------------------------------
// Block-diagonal projection.
// ---------------------------------------------------------------------------
__global__ __launch_bounds__(256)
void proj_kernel(const float* __restrict__ g, const float* __restrict__ wsum,
                 const float* __restrict__ W_val, const float* __restrict__ b_val,
                 float* __restrict__ samp)
{
    const int h  = blockIdx.y;
    const int r0 = blockIdx.x * 128;
    const int t  = threadIdx.x;
    const int d = t & 31, rg = t >> 5;

    __shared__ float Ws[256 * 32];
    __shared__ float As[128 * 36];

#pragma unroll
    for (int i = 0; i < 32; i++) {
        const int k = i * 8 + (t >> 5);
        Ws[k * 32 + d] = W_val[(size_t)k * 256 + h * 32 + d];
    }
    const float bv = b_val[h * 32 + d];

    float acc[16];
#pragma unroll
    for (int r = 0; r < 16; r++) acc[r] = 0.f;

    for (int kt = 0; kt < 8; kt++) {
        __syncthreads();
        {
            const int i = t >> 1, half = t & 1;
            const float* src = g + ((size_t)(r0 + i) * 8 + h) * 256 + kt * 32 + half * 16;
            float* dst = &As[i * 36 + half * 16];
#pragma unroll
            for (int q = 0; q < 4; q++)
                *(float4*)(dst + q * 4) = *(const float4*)(src + q * 4);
        }
        __syncthreads();

#pragma unroll
        for (int k = 0; k < 32; k++) {
            const float wv = Ws[(kt * 32 + k) * 32 + d];
#pragma unroll
            for (int r = 0; r < 16; r++)
                acc[r] = fmaf(As[(rg * 16 + r) * 36 + k], wv, acc[r]);
        }
    }

#pragma unroll
    for (int r = 0; r < 16; r++) {
        const int row = r0 + rg * 16 + r;
        samp[(size_t)row * 256 + h * 32 + d] = acc[r] + wsum[(size_t)row * 8 + h] * bv;
    }
}

// ---------------------------------------------------------------------------
extern "C" void kernel_launch(void* const* d_in, const int* in_sizes, int n_in,
                              void* d_out, int out_size)
{
    const float* query_embed = (const float*)d_in[0];
    const float* ctrl        = (const float*)d_in[1];
    const float* bev         = (const float*)d_in[2];
    /* d_in[3] spatial_shapes unused */
    const float* pc_range    = (const float*)d_in[4];
    const float* W_q   = (const float*)d_in[5];
    const float* b_q   = (const float*)d_in[6];
    const float* W_val = (const float*)d_in[7];
    const float* b_val = (const float*)d_in[8];
    const float* W_off = (const float*)d_in[9];
    const float* b_off = (const float*)d_in[10];
    const float* W_attn = (const float*)d_in[11];
    const float* b_attn = (const float*)d_in[12];
    const float* W_do  = (const float*)d_in[13];
    const float* b_do  = (const float*)d_in[14];
    const float* W_out = (const float*)d_in[15];
    const float* b_out = (const float*)d_in[16];
    float* out = (float*)d_out;

    float *pqoa, *pWaug, *pbaug, *pWfold, *pbfold, *pg, *pws, *ps;
    __half *pbTh;
    cudaGetSymbolAddress((void**)&pqoa,  g_qoa);
    cudaGetSymbolAddress((void**)&pWaug, g_Waug);
    cudaGetSymbolAddress((void**)&pbaug, g_baug);
    cudaGetSymbolAddress((void**)&pWfold, g_Wfold);
    cudaGetSymbolAddress((void**)&pbfold, g_bfold);
    cudaGetSymbolAddress((void**)&pg,    g_gath);
    cudaGetSymbolAddress((void**)&pws,   g_wsum);
    cudaGetSymbolAddress((void**)&pbTh,  g_bevTh);
    cudaGetSymbolAddress((void**)&ps,    g_samp);

    static cudaStream_t s1 = nullptr, s2 = nullptr;
    static cudaEvent_t evFork = nullptr, evT = nullptr, evS2 = nullptr;
    if (s1 == nullptr) {
        cudaStreamCreateWithFlags(&s1, cudaStreamNonBlocking);
        cudaStreamCreateWithFlags(&s2, cudaStreamNonBlocking);
        cudaEventCreateWithFlags(&evFork, cudaEventDisableTiming);
        cudaEventCreateWithFlags(&evT,    cudaEventDisableTiming);
        cudaEventCreateWithFlags(&evS2,   cudaEventDisableTiming);
    }

    cudaEventRecord(evFork, 0);
    cudaStreamWaitEvent(s1, evFork, 0);
    cudaStreamWaitEvent(s2, evFork, 0);

    // s1: monolithic DRAM-bound transpose (fp16 output)
    transpose_h<<<dim3(NHW / 64, DIM / 32, NB), 256, 0, s1>>>(bev, pbTh);
    cudaEventRecord(evT, s1);

    // s2: contention-free weight/bias folds for output GEMM
    prep_bfold<<<1, 256, 0, s2>>>(b_q, b_do, b_out, W_out, pbfold);
    fold8<<<64, 256, 0, s2>>>(W_do, W_q, W_out, pWfold);
    cudaEventRecord(evS2, s2);

    // main: offsets/logits path (split-K prep + 128-block GEMM)
    prep_w<<<257, 256>>>(W_q, W_off, W_attn, b_q, b_off, b_attn, pWaug, pbaug);
    gemm_qoa<<<dim3(NAUG / 64, NROWS / 64), 256>>>(query_embed, pWaug, pbaug, pqoa);

    cudaStreamWaitEvent(0, evT, 0);

    // gather (dedup, fp16, 4-deep pipelined) + per-head projection
    gather_kernel<<<NROWS, 256>>>(ctrl, pc_range, pbTh, pqoa, pg, pws);
    proj_kernel<<<dim3(NROWS / 128, NHEADS), 256>>>(pg, pws, W_val, b_val, ps);

    cudaStreamWaitEvent(0, evS2, 0);

    // out = samp@(W_do W_out) + qe@(W_q W_out) + b_fold
    gemm_dual64<<<dim3(DIM / 64, NROWS / 64), 256>>>(
        ps, query_embed, pWfold, pbfold, out);
}